// round 1
// baseline (speedup 1.0000x reference)
#include <cuda_runtime.h>
#include <math.h>

#define HIDDEN 1024
#define INNER  2048
#define STATE  16
#define BATCH  4
#define SEQ    2048
#define TOK    (BATCH*SEQ)   // 8192

// ---------------- scratch (static device globals; no runtime allocation) ----
__device__ float g_xn[TOK*HIDDEN];        // 33.5 MB  layernorm output
__device__ float g_xz[TOK*2*INNER];       // 134 MB   GEMM1 output [xb_raw | z]
__device__ float g_xb[TOK*INNER];         // 67 MB    conv+silu output
__device__ float g_dt[TOK*INNER];         // 67 MB    softplus(dt_pre)
__device__ float g_bc[TOK*2*STATE];       // 1 MB     [B(16) | C(16)] per token
__device__ float g_y [TOK*INNER];         // 67 MB    gated SSM output

// ---------------------------------------------------------------- LayerNorm
__global__ __launch_bounds__(256) void ln_kernel(
    const float* __restrict__ x, const float* __restrict__ g,
    const float* __restrict__ bt)
{
    int r = blockIdx.x, t = threadIdx.x;
    float4 v = *(const float4*)(x + (size_t)r*HIDDEN + t*4);
    float s  = v.x + v.y + v.z + v.w;
    float s2 = v.x*v.x + v.y*v.y + v.z*v.z + v.w*v.w;
    #pragma unroll
    for (int off = 16; off > 0; off >>= 1) {
        s  += __shfl_xor_sync(0xffffffffu, s,  off);
        s2 += __shfl_xor_sync(0xffffffffu, s2, off);
    }
    __shared__ float a1[8], a2[8];
    if ((t & 31) == 0) { a1[t >> 5] = s; a2[t >> 5] = s2; }
    __syncthreads();
    float ts = 0.f, ts2 = 0.f;
    #pragma unroll
    for (int i = 0; i < 8; i++) { ts += a1[i]; ts2 += a2[i]; }
    float mu   = ts * (1.f / HIDDEN);
    float var  = fmaf(ts2, 1.f / HIDDEN, -mu * mu);
    float rstd = rsqrtf(var + 1e-5f);
    float4 g4 = *(const float4*)(g  + t*4);
    float4 b4 = *(const float4*)(bt + t*4);
    float4 ov;
    ov.x = (v.x - mu) * rstd * g4.x + b4.x;
    ov.y = (v.y - mu) * rstd * g4.y + b4.y;
    ov.z = (v.z - mu) * rstd * g4.z + b4.z;
    ov.w = (v.w - mu) * rstd * g4.w + b4.w;
    *(float4*)(g_xn + (size_t)r*HIDDEN + t*4) = ov;
}

// ------------------------------------------------------------------- SGEMM
// C[M,N] = A[M,K] @ B[K,N], row-major. 128x128 tile, BK=8, 256 threads, 8x8/thr.
// EPI: 0 = plain, 1 = +bias then softplus, 2 = +residual
__device__ __forceinline__ float softplus_f(float v) {
    return fmaxf(v, 0.f) + __logf(1.f + __expf(-fabsf(v)));
}

template<int EPI>
__global__ __launch_bounds__(256) void sgemm128(
    const float* __restrict__ A, const float* __restrict__ B, float* __restrict__ C,
    int M, int N, int K,
    const float* __restrict__ bias, const float* __restrict__ resid)
{
    __shared__ float As[8][128];
    __shared__ float Bs[8][128];
    int bx = blockIdx.x, by = blockIdx.y, tid = threadIdx.x;

    int arow = tid >> 1, acol = (tid & 1) * 4;
    int brow = tid >> 5, bcol = (tid & 31) * 4;
    const float* Ap = A + (size_t)(by*128 + arow)*K + acol;
    const float* Bp = B + (size_t)brow*N + bx*128 + bcol;

    int tx = tid & 15, ty = tid >> 4;
    float acc[8][8] = {};

    for (int k0 = 0; k0 < K; k0 += 8) {
        float4 av = *(const float4*)Ap;
        float4 bv = *(const float4*)Bp;
        As[acol+0][arow] = av.x;
        As[acol+1][arow] = av.y;
        As[acol+2][arow] = av.z;
        As[acol+3][arow] = av.w;
        *(float4*)&Bs[brow][bcol] = bv;
        __syncthreads();
        #pragma unroll
        for (int kk = 0; kk < 8; kk++) {
            float ra[8], rb[8];
            *(float4*)(ra)   = *(const float4*)&As[kk][ty*8];
            *(float4*)(ra+4) = *(const float4*)&As[kk][ty*8+4];
            *(float4*)(rb)   = *(const float4*)&Bs[kk][tx*8];
            *(float4*)(rb+4) = *(const float4*)&Bs[kk][tx*8+4];
            #pragma unroll
            for (int i = 0; i < 8; i++)
                #pragma unroll
                for (int j = 0; j < 8; j++)
                    acc[i][j] = fmaf(ra[i], rb[j], acc[i][j]);
        }
        __syncthreads();
        Ap += 8;
        Bp += (size_t)8 * N;
    }

    #pragma unroll
    for (int i = 0; i < 8; i++) {
        int row = by*128 + ty*8 + i;
        float* crow = C + (size_t)row*N + bx*128 + tx*8;
        #pragma unroll
        for (int j = 0; j < 8; j += 4) {
            float4 v = make_float4(acc[i][j], acc[i][j+1], acc[i][j+2], acc[i][j+3]);
            if (EPI == 1) {
                int c = bx*128 + tx*8 + j;
                float4 bb = *(const float4*)(bias + c);
                v.x = softplus_f(v.x + bb.x);
                v.y = softplus_f(v.y + bb.y);
                v.z = softplus_f(v.z + bb.z);
                v.w = softplus_f(v.w + bb.w);
            } else if (EPI == 2) {
                float4 rr = *(const float4*)(resid + (size_t)row*N + bx*128 + tx*8 + j);
                v.x += rr.x; v.y += rr.y; v.z += rr.z; v.w += rr.w;
            }
            *(float4*)(crow + j) = v;
        }
    }
}

// ----------------------------------------------- depthwise conv (k=3) + SiLU
__global__ __launch_bounds__(256) void conv_kernel(
    const float* __restrict__ cw, const float* __restrict__ cb)
{
    int idx = blockIdx.x * 256 + threadIdx.x;     // TOK * INNER/4 = 4194304
    int d4 = idx & 511;
    int r  = idx >> 9;
    int l  = r & (SEQ - 1);
    const float* base = g_xz + (size_t)r*(2*INNER) + d4*4;
    float4 zero = make_float4(0.f, 0.f, 0.f, 0.f);
    float4 xm = (l > 0)       ? *(const float4*)(base - 2*INNER) : zero;
    float4 xc = *(const float4*)(base);
    float4 xp = (l < SEQ - 1) ? *(const float4*)(base + 2*INNER) : zero;
    const float4* cwp = (const float4*)(cw + d4*12);   // 4 channels x 3 taps
    float4 t0 = cwp[0], t1 = cwp[1], t2 = cwp[2];
    float4 b4 = *(const float4*)(cb + d4*4);
    float o0 = t0.x*xm.x + t0.y*xc.x + t0.z*xp.x + b4.x;
    float o1 = t0.w*xm.y + t1.x*xc.y + t1.y*xp.y + b4.y;
    float o2 = t1.z*xm.z + t1.w*xc.z + t2.x*xp.z + b4.z;
    float o3 = t2.y*xm.w + t2.z*xc.w + t2.w*xp.w + b4.w;
    o0 *= __fdividef(1.f, 1.f + __expf(-o0));
    o1 *= __fdividef(1.f, 1.f + __expf(-o1));
    o2 *= __fdividef(1.f, 1.f + __expf(-o2));
    o3 *= __fdividef(1.f, 1.f + __expf(-o3));
    *(float4*)(g_xb + (size_t)r*INNER + d4*4) = make_float4(o0, o1, o2, o3);
}

// --------------------------------------------- skinny GEMM: B = xb@W_B, C = xb@W_C
__global__ __launch_bounds__(256) void bc_kernel(
    const float* __restrict__ WB, const float* __restrict__ WC)
{
    __shared__ float xs[INNER];
    __shared__ float red[8][32];
    int r = blockIdx.x, tid = threadIdx.x;
    const float* row = g_xb + (size_t)r*INNER;
    for (int i = tid; i < INNER/4; i += 256)
        ((float4*)xs)[i] = ((const float4*)row)[i];
    __syncthreads();
    int j = tid & 31, s = tid >> 5;
    const float* W = (j < STATE) ? (WB + j) : (WC + (j - STATE));
    float acc = 0.f;
    int k0 = s * 256;
    #pragma unroll 4
    for (int k = k0; k < k0 + 256; k++)
        acc = fmaf(xs[k], W[(size_t)k*STATE], acc);
    red[s][j] = acc;
    __syncthreads();
    if (s == 0) {
        float tot = 0.f;
        #pragma unroll
        for (int i = 0; i < 8; i++) tot += red[i][j];
        g_bc[(size_t)r*2*STATE + j] = tot;
    }
}

// ---------------------------------------------------- selective scan + gating
// thread = (b, d, q), q in 0..7 owning states 2q, 2q+1. 65536 threads.
__global__ __launch_bounds__(256) void scan_kernel(
    const float* __restrict__ A_log, const float* __restrict__ Dp)
{
    int t = blockIdx.x * 256 + threadIdx.x;
    int q = t & 7;
    int d = (t >> 3) & (INNER - 1);
    int b = t >> 14;
    int n0 = q * 2;

    float a0 = -__expf(A_log[d*STATE + n0]);
    float a1 = -__expf(A_log[d*STATE + n0 + 1]);
    float Dd = Dp[d];

    size_t rb = (size_t)b * SEQ;
    const float* dtp = g_dt + rb*INNER + d;
    const float* xp  = g_xb + rb*INNER + d;
    const float* bcp = g_bc + rb*(2*STATE) + n0;
    const float* zp  = g_xz + rb*(2*INNER) + INNER + d;
    float*       yp  = g_y  + rb*INNER + d;

    float h0 = 0.f, h1 = 0.f;
    float dtc = *dtp, xc = *xp;
    float2 Bv = *(const float2*)bcp;
    float2 Cv = *(const float2*)(bcp + STATE);

    for (int l = 0; l < SEQ; l++) {
        dtp += INNER; xp += INNER; bcp += 2*STATE;
        float dtn = 0.f, xn2 = 0.f;
        float2 Bn = make_float2(0.f, 0.f), Cn = make_float2(0.f, 0.f);
        if (l < SEQ - 1) {
            dtn = *dtp; xn2 = *xp;
            Bn = *(const float2*)bcp;
            Cn = *(const float2*)(bcp + STATE);
        }
        float e0 = __expf(dtc * a0);
        float e1 = __expf(dtc * a1);
        float dx = dtc * xc;
        h0 = fmaf(e0, h0, dx * Bv.x);
        h1 = fmaf(e1, h1, dx * Bv.y);
        float p = fmaf(h1, Cv.y, h0 * Cv.x);
        p += __shfl_xor_sync(0xffffffffu, p, 1);
        p += __shfl_xor_sync(0xffffffffu, p, 2);
        p += __shfl_xor_sync(0xffffffffu, p, 4);
        if (q == 0) {
            float zz  = *zp;
            float sil = zz * __fdividef(1.f, 1.f + __expf(-zz));
            *yp = (p + Dd * xc) * sil;
        }
        zp += 2*INNER; yp += INNER;
        dtc = dtn; xc = xn2; Bv = Bn; Cv = Cn;
    }
}

// ------------------------------------------------------------------- launch
extern "C" void kernel_launch(void* const* d_in, const int* in_sizes, int n_in,
                              void* d_out, int out_size)
{
    const float* x    = (const float*)d_in[0];
    const float* ns   = (const float*)d_in[1];
    const float* nb   = (const float*)d_in[2];
    const float* Win  = (const float*)d_in[3];
    const float* cw   = (const float*)d_in[4];
    const float* cb   = (const float*)d_in[5];
    const float* Wdt  = (const float*)d_in[6];
    const float* bdt  = (const float*)d_in[7];
    const float* Alog = (const float*)d_in[8];
    const float* Dp   = (const float*)d_in[9];
    const float* WB   = (const float*)d_in[10];
    const float* WC   = (const float*)d_in[11];
    const float* Wout = (const float*)d_in[12];
    float* out = (float*)d_out;

    void *p_xn, *p_xz, *p_xb, *p_dt, *p_y;
    cudaGetSymbolAddress(&p_xn, g_xn);
    cudaGetSymbolAddress(&p_xz, g_xz);
    cudaGetSymbolAddress(&p_xb, g_xb);
    cudaGetSymbolAddress(&p_dt, g_dt);
    cudaGetSymbolAddress(&p_y,  g_y);
    float* xn = (float*)p_xn;
    float* xz = (float*)p_xz;
    float* xb = (float*)p_xb;
    float* dt = (float*)p_dt;
    float* yv = (float*)p_y;

    // 1) LayerNorm
    ln_kernel<<<TOK, 256>>>(x, ns, nb);
    // 2) xz = xn @ W_in   [8192 x 4096, K=1024]
    sgemm128<0><<<dim3(2*INNER/128, TOK/128), 256>>>(
        xn, Win, xz, TOK, 2*INNER, HIDDEN, nullptr, nullptr);
    // 3) depthwise conv + SiLU -> g_xb
    conv_kernel<<<(TOK*INNER/4)/256, 256>>>(cw, cb);
    // 4) dt = softplus(xb @ W_dt + b_dt)   [8192 x 2048, K=2048]
    sgemm128<1><<<dim3(INNER/128, TOK/128), 256>>>(
        xb, Wdt, dt, TOK, INNER, INNER, bdt, nullptr);
    // 5) B,C = xb @ [W_B | W_C]
    bc_kernel<<<TOK, 256>>>(WB, WC);
    // 6) selective scan + gating -> g_y
    scan_kernel<<<(BATCH*INNER*8)/256, 256>>>(Alog, Dp);
    // 7) out = x + y @ W_out   [8192 x 1024, K=2048]
    sgemm128<2><<<dim3(HIDDEN/128, TOK/128), 256>>>(
        yv, Wout, out, TOK, HIDDEN, INNER, nullptr, x);
}

// round 3
// speedup vs baseline: 2.0488x; 2.0488x over previous
#include <cuda_runtime.h>
#include <cstdint>
#include <math.h>

#define HIDDEN 1024
#define INNER  2048
#define STATE  16
#define BATCH  4
#define SEQ    2048
#define TOK    (BATCH*SEQ)   // 8192

// ---------------- scratch (static device globals; no runtime allocation) ----
__device__ float g_xn[TOK*HIDDEN];        // layernorm output
__device__ float g_xz[TOK*2*INNER];       // GEMM1 output [xb_raw | z]
__device__ float g_xb[TOK*INNER];         // conv+silu output
__device__ float g_dt[TOK*INNER];         // softplus(dt_pre)
__device__ float g_bc[TOK*2*STATE];       // [B(16) | C(16)] per token
__device__ float g_y [TOK*INNER];         // gated SSM output
__device__ float g_WinT [2*INNER*HIDDEN]; // W_in^T  [4096,1024]
__device__ float g_WdtT [INNER*INNER];    // W_dt^T  [2048,2048]
__device__ float g_WoutT[HIDDEN*INNER];   // W_out^T [1024,2048]

// ============================== helpers =====================================
__device__ __forceinline__ float tf32r(float x) {
    float r; asm("cvt.rna.tf32.f32 %0, %1;" : "=f"(r) : "f"(x)); return r;
}
__device__ __forceinline__ void cp16(uint32_t s, const void* g) {
    asm volatile("cp.async.cg.shared.global [%0], [%1], 16;" :: "r"(s), "l"(g));
}
__device__ __forceinline__ void cp_commit() {
    asm volatile("cp.async.commit_group;" ::: "memory");
}
template<int N> __device__ __forceinline__ void cp_wait() {
    asm volatile("cp.async.wait_group %0;" :: "n"(N) : "memory");
}
__device__ __forceinline__ void mma_tf32(float* d, const uint32_t* a, const uint32_t* b) {
    asm volatile("mma.sync.aligned.m16n8k8.row.col.f32.tf32.tf32.f32 "
                 "{%0,%1,%2,%3},{%4,%5,%6,%7},{%8,%9},{%0,%1,%2,%3};"
                 : "+f"(d[0]), "+f"(d[1]), "+f"(d[2]), "+f"(d[3])
                 : "r"(a[0]), "r"(a[1]), "r"(a[2]), "r"(a[3]), "r"(b[0]), "r"(b[1]));
}
__device__ __forceinline__ float softplus_f(float v) {
    return fmaxf(v, 0.f) + __logf(1.f + __expf(-fabsf(v)));
}

// ====================== tf32 mma.sync GEMM ==================================
// C[M,N] = A[M,K] @ Bt[N,K]^T, row-major A and Bt.
// BM=BN=128, BK=16, 256 threads (8 warps: 2m x 4n), warp tile 64x32.
// smem rows padded to 20 floats -> conflict-free fragment LDS.
// EPI: 0 plain, 1 +bias->softplus, 2 +residual
#define PAD 20

template<int EPI>
__global__ __launch_bounds__(256) void gemm_mma(
    const float* __restrict__ A, const float* __restrict__ Bt, float* __restrict__ C,
    int M, int N, int K,
    const float* __restrict__ bias, const float* __restrict__ resid)
{
    __shared__ float As[2][128*PAD];
    __shared__ float Bs[2][128*PAD];

    int tid = threadIdx.x, lane = tid & 31, wid = tid >> 5;
    int wm = wid >> 2, wn = wid & 3;          // 2 x 4 warp grid
    int m0 = blockIdx.y * 128, n0 = blockIdx.x * 128;

    int srow = tid >> 2, sc4 = tid & 3;       // staging: thread -> (row, float4)
    uint32_t sA0 = (uint32_t)__cvta_generic_to_shared(&As[0][0]);
    uint32_t sB0 = (uint32_t)__cvta_generic_to_shared(&Bs[0][0]);

    const float* Agm = A  + (size_t)(m0 + srow) * K + sc4 * 4;
    const float* Bgm = Bt + (size_t)(n0 + srow) * K + sc4 * 4;
    const float* Agm2 = Agm + (size_t)64 * K;       // rows 64..127 (second half)
    const float* Bgm2 = Bgm + (size_t)64 * K;
    uint32_t offs1 = (srow * PAD + sc4 * 4) * 4;
    uint32_t offs2 = ((srow + 64) * PAD + sc4 * 4) * 4;

    int ns = K >> 4;

    // prefetch stage 0
    {
        cp16(sA0 + offs1, Agm);  cp16(sA0 + offs2, Agm2);
        cp16(sB0 + offs1, Bgm);  cp16(sB0 + offs2, Bgm2);
        cp_commit();
    }

    float acc[4][4][4] = {};
    int r = lane >> 2, c = lane & 3;

    for (int s = 0; s < ns; s++) {
        int buf = s & 1;
        if (s + 1 < ns) {
            int nb = (s + 1) & 1;
            uint32_t bofs = nb ? (uint32_t)(128*PAD*4) : 0u;
            const float* a1 = Agm  + (s + 1) * 16;
            const float* a2 = Agm2 + (s + 1) * 16;
            const float* b1 = Bgm  + (s + 1) * 16;
            const float* b2 = Bgm2 + (s + 1) * 16;
            cp16(sA0 + bofs + offs1, a1);  cp16(sA0 + bofs + offs2, a2);
            cp16(sB0 + bofs + offs1, b1);  cp16(sB0 + bofs + offs2, b2);
            cp_commit();
            cp_wait<1>();
        } else {
            cp_wait<0>();
        }
        __syncthreads();

        const float* Ab = &As[buf][0];
        const float* Bb = &Bs[buf][0];
        #pragma unroll
        for (int ks = 0; ks < 2; ks++) {
            uint32_t af[4][4], bf[4][2];
            #pragma unroll
            for (int am = 0; am < 4; am++) {
                const float* p = Ab + (wm*64 + am*16 + r) * PAD + ks*8 + c;
                af[am][0] = __float_as_uint(p[0]);
                af[am][1] = __float_as_uint(p[8*PAD]);
                af[am][2] = __float_as_uint(p[4]);
                af[am][3] = __float_as_uint(p[8*PAD + 4]);
            }
            #pragma unroll
            for (int bn = 0; bn < 4; bn++) {
                const float* p = Bb + (wn*32 + bn*8 + r) * PAD + ks*8 + c;
                bf[bn][0] = __float_as_uint(p[0]);
                bf[bn][1] = __float_as_uint(p[4]);
            }
            #pragma unroll
            for (int am = 0; am < 4; am++)
                #pragma unroll
                for (int bn = 0; bn < 4; bn++)
                    mma_tf32(acc[am][bn], af[am], bf[bn]);
        }
        __syncthreads();
    }

    // ------------------------------- epilogue -------------------------------
    #pragma unroll
    for (int am = 0; am < 4; am++) {
        int row0 = m0 + wm*64 + am*16 + r;
        #pragma unroll
        for (int bn = 0; bn < 4; bn++) {
            int col = n0 + wn*32 + bn*8 + 2*c;
            #pragma unroll
            for (int h = 0; h < 2; h++) {          // h=0: row0, h=1: row0+8
                int row = row0 + h*8;
                float v0 = acc[am][bn][h*2 + 0];
                float v1 = acc[am][bn][h*2 + 1];
                if (EPI == 1) {
                    v0 = softplus_f(v0 + bias[col]);
                    v1 = softplus_f(v1 + bias[col + 1]);
                } else if (EPI == 2) {
                    const float* rp = resid + (size_t)row * N + col;
                    v0 += rp[0]; v1 += rp[1];
                }
                *(float2*)(C + (size_t)row * N + col) = make_float2(v0, v1);
            }
        }
    }
}

// ------------------------------- weight transpose (with tf32 pre-round) ----
__global__ __launch_bounds__(256) void transpose_kernel(
    const float* __restrict__ in, float* __restrict__ out, int K, int N)
{   // in [K,N] -> out [N,K]
    __shared__ float tile[32][33];
    int tx = threadIdx.x, ty = threadIdx.y;
    int x = blockIdx.x * 32 + tx;      // n
    int y = blockIdx.y * 32 + ty;      // k
    #pragma unroll
    for (int j = 0; j < 32; j += 8)
        tile[ty + j][tx] = in[(size_t)(y + j) * N + x];
    __syncthreads();
    int x2 = blockIdx.y * 32 + tx;     // k
    int y2 = blockIdx.x * 32 + ty;     // n
    #pragma unroll
    for (int j = 0; j < 32; j += 8)
        out[(size_t)(y2 + j) * K + x2] = tf32r(tile[tx][ty + j]);
}

// ---------------------------------------------------------------- LayerNorm
__global__ __launch_bounds__(256) void ln_kernel(
    const float* __restrict__ x, const float* __restrict__ g,
    const float* __restrict__ bt)
{
    int r = blockIdx.x, t = threadIdx.x;
    float4 v = *(const float4*)(x + (size_t)r*HIDDEN + t*4);
    float s  = v.x + v.y + v.z + v.w;
    float s2 = v.x*v.x + v.y*v.y + v.z*v.z + v.w*v.w;
    #pragma unroll
    for (int off = 16; off > 0; off >>= 1) {
        s  += __shfl_xor_sync(0xffffffffu, s,  off);
        s2 += __shfl_xor_sync(0xffffffffu, s2, off);
    }
    __shared__ float a1[8], a2[8];
    if ((t & 31) == 0) { a1[t >> 5] = s; a2[t >> 5] = s2; }
    __syncthreads();
    float ts = 0.f, ts2 = 0.f;
    #pragma unroll
    for (int i = 0; i < 8; i++) { ts += a1[i]; ts2 += a2[i]; }
    float mu   = ts * (1.f / HIDDEN);
    float var  = fmaf(ts2, 1.f / HIDDEN, -mu * mu);
    float rstd = rsqrtf(var + 1e-5f);
    float4 g4 = *(const float4*)(g  + t*4);
    float4 b4 = *(const float4*)(bt + t*4);
    float4 ov;
    ov.x = (v.x - mu) * rstd * g4.x + b4.x;
    ov.y = (v.y - mu) * rstd * g4.y + b4.y;
    ov.z = (v.z - mu) * rstd * g4.z + b4.z;
    ov.w = (v.w - mu) * rstd * g4.w + b4.w;
    *(float4*)(g_xn + (size_t)r*HIDDEN + t*4) = ov;
}

// ----------------------------------------------- depthwise conv (k=3) + SiLU
__global__ __launch_bounds__(256) void conv_kernel(
    const float* __restrict__ cw, const float* __restrict__ cb)
{
    int idx = blockIdx.x * 256 + threadIdx.x;
    int d4 = idx & 511;
    int r  = idx >> 9;
    int l  = r & (SEQ - 1);
    const float* base = g_xz + (size_t)r*(2*INNER) + d4*4;
    float4 zero = make_float4(0.f, 0.f, 0.f, 0.f);
    float4 xm = (l > 0)       ? *(const float4*)(base - 2*INNER) : zero;
    float4 xc = *(const float4*)(base);
    float4 xp = (l < SEQ - 1) ? *(const float4*)(base + 2*INNER) : zero;
    const float4* cwp = (const float4*)(cw + d4*12);
    float4 t0 = cwp[0], t1 = cwp[1], t2 = cwp[2];
    float4 b4 = *(const float4*)(cb + d4*4);
    float o0 = t0.x*xm.x + t0.y*xc.x + t0.z*xp.x + b4.x;
    float o1 = t0.w*xm.y + t1.x*xc.y + t1.y*xp.y + b4.y;
    float o2 = t1.z*xm.z + t1.w*xc.z + t2.x*xp.z + b4.z;
    float o3 = t2.y*xm.w + t2.z*xc.w + t2.w*xp.w + b4.w;
    o0 *= __fdividef(1.f, 1.f + __expf(-o0));
    o1 *= __fdividef(1.f, 1.f + __expf(-o1));
    o2 *= __fdividef(1.f, 1.f + __expf(-o2));
    o3 *= __fdividef(1.f, 1.f + __expf(-o3));
    *(float4*)(g_xb + (size_t)r*INNER + d4*4) = make_float4(o0, o1, o2, o3);
}

// --------------------------------------------- skinny GEMM: B,C projections
__global__ __launch_bounds__(256) void bc_kernel(
    const float* __restrict__ WB, const float* __restrict__ WC)
{
    __shared__ float xs[INNER];
    __shared__ float red[8][32];
    int r = blockIdx.x, tid = threadIdx.x;
    const float* row = g_xb + (size_t)r*INNER;
    for (int i = tid; i < INNER/4; i += 256)
        ((float4*)xs)[i] = ((const float4*)row)[i];
    __syncthreads();
    int j = tid & 31, s = tid >> 5;
    const float* W = (j < STATE) ? (WB + j) : (WC + (j - STATE));
    float acc = 0.f;
    int k0 = s * 256;
    #pragma unroll 4
    for (int k = k0; k < k0 + 256; k++)
        acc = fmaf(xs[k], W[(size_t)k*STATE], acc);
    red[s][j] = acc;
    __syncthreads();
    if (s == 0) {
        float tot = 0.f;
        #pragma unroll
        for (int i = 0; i < 8; i++) tot += red[i][j];
        g_bc[(size_t)r*2*STATE + j] = tot;
    }
}

// ---------------------------------------------------- selective scan + gating
__global__ __launch_bounds__(256) void scan_kernel(
    const float* __restrict__ A_log, const float* __restrict__ Dp)
{
    int t = blockIdx.x * 256 + threadIdx.x;
    int q = t & 7;
    int d = (t >> 3) & (INNER - 1);
    int b = t >> 14;
    int n0 = q * 2;

    float a0 = -__expf(A_log[d*STATE + n0]);
    float a1 = -__expf(A_log[d*STATE + n0 + 1]);
    float Dd = Dp[d];

    size_t rb = (size_t)b * SEQ;
    const float* dtp = g_dt + rb*INNER + d;
    const float* xp  = g_xb + rb*INNER + d;
    const float* bcp = g_bc + rb*(2*STATE) + n0;
    const float* zp  = g_xz + rb*(2*INNER) + INNER + d;
    float*       yp  = g_y  + rb*INNER + d;

    float h0 = 0.f, h1 = 0.f;
    float dtc = *dtp, xc = *xp;
    float2 Bv = *(const float2*)bcp;
    float2 Cv = *(const float2*)(bcp + STATE);

    for (int l = 0; l < SEQ; l++) {
        dtp += INNER; xp += INNER; bcp += 2*STATE;
        float dtn = 0.f, xn2 = 0.f;
        float2 Bn = make_float2(0.f, 0.f), Cn = make_float2(0.f, 0.f);
        if (l < SEQ - 1) {
            dtn = *dtp; xn2 = *xp;
            Bn = *(const float2*)bcp;
            Cn = *(const float2*)(bcp + STATE);
        }
        float e0 = __expf(dtc * a0);
        float e1 = __expf(dtc * a1);
        float dx = dtc * xc;
        h0 = fmaf(e0, h0, dx * Bv.x);
        h1 = fmaf(e1, h1, dx * Bv.y);
        float p = fmaf(h1, Cv.y, h0 * Cv.x);
        p += __shfl_xor_sync(0xffffffffu, p, 1);
        p += __shfl_xor_sync(0xffffffffu, p, 2);
        p += __shfl_xor_sync(0xffffffffu, p, 4);
        if (q == 0) {
            float zz  = *zp;
            float sil = zz * __fdividef(1.f, 1.f + __expf(-zz));
            *yp = (p + Dd * xc) * sil;
        }
        zp += 2*INNER; yp += INNER;
        dtc = dtn; xc = xn2; Bv = Bn; Cv = Cn;
    }
}

// ------------------------------------------------------------------- launch
extern "C" void kernel_launch(void* const* d_in, const int* in_sizes, int n_in,
                              void* d_out, int out_size)
{
    const float* x    = (const float*)d_in[0];
    const float* ns   = (const float*)d_in[1];
    const float* nb   = (const float*)d_in[2];
    const float* Win  = (const float*)d_in[3];
    const float* cw   = (const float*)d_in[4];
    const float* cb   = (const float*)d_in[5];
    const float* Wdt  = (const float*)d_in[6];
    const float* bdt  = (const float*)d_in[7];
    const float* Alog = (const float*)d_in[8];
    const float* Dp   = (const float*)d_in[9];
    const float* WB   = (const float*)d_in[10];
    const float* WC   = (const float*)d_in[11];
    const float* Wout = (const float*)d_in[12];
    float* out = (float*)d_out;

    void *p_xn, *p_xz, *p_xb, *p_dt, *p_y, *p_wint, *p_wdtt, *p_woutt;
    cudaGetSymbolAddress(&p_xn, g_xn);
    cudaGetSymbolAddress(&p_xz, g_xz);
    cudaGetSymbolAddress(&p_xb, g_xb);
    cudaGetSymbolAddress(&p_dt, g_dt);
    cudaGetSymbolAddress(&p_y,  g_y);
    cudaGetSymbolAddress(&p_wint,  g_WinT);
    cudaGetSymbolAddress(&p_wdtt,  g_WdtT);
    cudaGetSymbolAddress(&p_woutt, g_WoutT);
    float* xn = (float*)p_xn;   float* xz = (float*)p_xz;
    float* xb = (float*)p_xb;   float* dt = (float*)p_dt;
    float* yv = (float*)p_y;
    float* WinT  = (float*)p_wint;
    float* WdtT  = (float*)p_wdtt;
    float* WoutT = (float*)p_woutt;

    // 0) weight transposes (tf32-rounded)
    transpose_kernel<<<dim3(2*INNER/32, HIDDEN/32), dim3(32,8)>>>(Win,  WinT,  HIDDEN, 2*INNER);
    transpose_kernel<<<dim3(INNER/32,   INNER/32),  dim3(32,8)>>>(Wdt,  WdtT,  INNER,  INNER);
    transpose_kernel<<<dim3(HIDDEN/32,  INNER/32),  dim3(32,8)>>>(Wout, WoutT, INNER,  HIDDEN);
    // 1) LayerNorm
    ln_kernel<<<TOK, 256>>>(x, ns, nb);
    // 2) xz = xn @ W_in
    gemm_mma<0><<<dim3(2*INNER/128, TOK/128), 256>>>(
        xn, WinT, xz, TOK, 2*INNER, HIDDEN, nullptr, nullptr);
    // 3) conv + SiLU
    conv_kernel<<<(TOK*INNER/4)/256, 256>>>(cw, cb);
    // 4) dt = softplus(xb @ W_dt + b_dt)
    gemm_mma<1><<<dim3(INNER/128, TOK/128), 256>>>(
        xb, WdtT, dt, TOK, INNER, INNER, bdt, nullptr);
    // 5) B,C projections
    bc_kernel<<<TOK, 256>>>(WB, WC);
    // 6) selective scan + gating
    scan_kernel<<<(BATCH*INNER*8)/256, 256>>>(Alog, Dp);
    // 7) out = x + y @ W_out
    gemm_mma<2><<<dim3(HIDDEN/128, TOK/128), 256>>>(
        yv, WoutT, out, TOK, HIDDEN, INNER, nullptr, x);
}

// round 6
// speedup vs baseline: 3.0108x; 1.4695x over previous
#include <cuda_runtime.h>
#include <cstdint>
#include <math.h>

#define HIDDEN 1024
#define INNER  2048
#define STATE  16
#define BATCH  4
#define SEQ    2048
#define TOK    (BATCH*SEQ)   // 8192
#define NCAT   2176          // 2048 dt | 16 B | 16 C | 96 pad (17 tiles of 128)

// ---------------- scratch (static device globals) ---------------------------
__device__ float g_xn[TOK*HIDDEN];
__device__ float g_xz[TOK*2*INNER];       // [xb_raw | z]
__device__ float g_xb[TOK*INNER];
__device__ float g_dtbc[TOK*NCAT];        // [softplus(dt)(2048) | B(16) | C(16) | pad]
__device__ float g_y [TOK*INNER];
__device__ float g_WinT [2*INNER*HIDDEN];
__device__ float g_WcatT[NCAT*INNER];     // [WdtT ; WB^T ; WC^T ; zeros]
__device__ float g_WoutT[HIDDEN*INNER];

// ============================== helpers =====================================
__device__ __forceinline__ float tf32r(float x) {
    float r; asm("cvt.rna.tf32.f32 %0, %1;" : "=f"(r) : "f"(x)); return r;
}
__device__ __forceinline__ void cp16(uint32_t s, const void* g) {
    asm volatile("cp.async.cg.shared.global [%0], [%1], 16;" :: "r"(s), "l"(g));
}
__device__ __forceinline__ void cp_commit() {
    asm volatile("cp.async.commit_group;" ::: "memory");
}
template<int N> __device__ __forceinline__ void cp_wait() {
    asm volatile("cp.async.wait_group %0;" :: "n"(N) : "memory");
}
__device__ __forceinline__ void mma_tf32(float* d, const uint32_t* a, const uint32_t* b) {
    asm volatile("mma.sync.aligned.m16n8k8.row.col.f32.tf32.tf32.f32 "
                 "{%0,%1,%2,%3},{%4,%5,%6,%7},{%8,%9},{%0,%1,%2,%3};"
                 : "+f"(d[0]), "+f"(d[1]), "+f"(d[2]), "+f"(d[3])
                 : "r"(a[0]), "r"(a[1]), "r"(a[2]), "r"(a[3]), "r"(b[0]), "r"(b[1]));
}
__device__ __forceinline__ float softplus_f(float v) {
    return fmaxf(v, 0.f) + __logf(1.f + __expf(-fabsf(v)));
}

// ====================== tf32 mma.sync GEMM ==================================
// C[M,N] = A[M,K] @ Bt[N,K]^T. BM=BN=128, BK=16, 128 threads (4 warps, 2x2),
// warp tile 64x64. EPI: 0 plain, 1 mixed softplus(dt)|raw(bc), 2 +residual
#define PAD 20

template<int EPI>
__global__ __launch_bounds__(128) void gemm_mma(
    const float* __restrict__ A, const float* __restrict__ Bt, float* __restrict__ C,
    int M, int N, int K,
    const float* __restrict__ bias, const float* __restrict__ resid)
{
    __shared__ float As[2][128*PAD];
    __shared__ float Bs[2][128*PAD];

    int tid = threadIdx.x, lane = tid & 31, wid = tid >> 5;
    int wm = wid >> 1, wn = wid & 1;          // 2 x 2 warp grid, 64x64 tiles
    int m0 = blockIdx.y * 128, n0 = blockIdx.x * 128;

    int srow = tid >> 2, sc4 = tid & 3;       // staging rows 0..31 (+32*i)
    uint32_t sA0 = (uint32_t)__cvta_generic_to_shared(&As[0][0]);
    uint32_t sB0 = (uint32_t)__cvta_generic_to_shared(&Bs[0][0]);

    const float* Agm = A  + (size_t)(m0 + srow) * K + sc4 * 4;
    const float* Bgm = Bt + (size_t)(n0 + srow) * K + sc4 * 4;
    uint32_t offs[4];
    #pragma unroll
    for (int i = 0; i < 4; i++) offs[i] = ((srow + 32*i) * PAD + sc4 * 4) * 4;

    int ns = K >> 4;

    // prefetch stage 0
    #pragma unroll
    for (int i = 0; i < 4; i++) {
        cp16(sA0 + offs[i], Agm + (size_t)(32*i) * K);
        cp16(sB0 + offs[i], Bgm + (size_t)(32*i) * K);
    }
    cp_commit();

    float acc[4][8][4] = {};
    int r = lane >> 2, c = lane & 3;

    for (int s = 0; s < ns; s++) {
        int buf = s & 1;
        if (s + 1 < ns) {
            uint32_t bofs = ((s + 1) & 1) ? (uint32_t)(128*PAD*4) : 0u;
            const float* a1 = Agm + (s + 1) * 16;
            const float* b1 = Bgm + (s + 1) * 16;
            #pragma unroll
            for (int i = 0; i < 4; i++) {
                cp16(sA0 + bofs + offs[i], a1 + (size_t)(32*i) * K);
                cp16(sB0 + bofs + offs[i], b1 + (size_t)(32*i) * K);
            }
            cp_commit();
            cp_wait<1>();
        } else {
            cp_wait<0>();
        }
        __syncthreads();

        const float* Ab = &As[buf][0];
        const float* Bb = &Bs[buf][0];
        #pragma unroll
        for (int ks = 0; ks < 2; ks++) {
            uint32_t af[4][4], bf[8][2];
            #pragma unroll
            for (int am = 0; am < 4; am++) {
                const float* p = Ab + (wm*64 + am*16 + r) * PAD + ks*8 + c;
                af[am][0] = __float_as_uint(p[0]);
                af[am][1] = __float_as_uint(p[8*PAD]);
                af[am][2] = __float_as_uint(p[4]);
                af[am][3] = __float_as_uint(p[8*PAD + 4]);
            }
            #pragma unroll
            for (int bn = 0; bn < 8; bn++) {
                const float* p = Bb + (wn*64 + bn*8 + r) * PAD + ks*8 + c;
                bf[bn][0] = __float_as_uint(p[0]);
                bf[bn][1] = __float_as_uint(p[4]);
            }
            #pragma unroll
            for (int am = 0; am < 4; am++)
                #pragma unroll
                for (int bn = 0; bn < 8; bn++)
                    mma_tf32(acc[am][bn], af[am], bf[bn]);
        }
        __syncthreads();
    }

    // ------------------------------- epilogue -------------------------------
    #pragma unroll
    for (int am = 0; am < 4; am++) {
        int row0 = m0 + wm*64 + am*16 + r;
        #pragma unroll
        for (int bn = 0; bn < 8; bn++) {
            int col = n0 + wn*64 + bn*8 + 2*c;
            #pragma unroll
            for (int h = 0; h < 2; h++) {
                int row = row0 + h*8;
                float v0 = acc[am][bn][h*2 + 0];
                float v1 = acc[am][bn][h*2 + 1];
                if (EPI == 1) {
                    if (col < 2048) {           // dt columns: bias + softplus
                        v0 = softplus_f(v0 + bias[col]);
                        v1 = softplus_f(v1 + bias[col + 1]);
                    }                            // bc/pad columns: raw
                } else if (EPI == 2) {
                    const float* rp = resid + (size_t)row * N + col;
                    v0 += rp[0]; v1 += rp[1];
                }
                *(float2*)(C + (size_t)row * N + col) = make_float2(v0, v1);
            }
        }
    }
}

// ------------------------------- weight prep --------------------------------
__global__ __launch_bounds__(256) void transpose_kernel(
    const float* __restrict__ in, float* __restrict__ out, int K, int N)
{   // in [K,N] -> out [N,K], tf32-rounded
    __shared__ float tile[32][33];
    int tx = threadIdx.x, ty = threadIdx.y;
    int x = blockIdx.x * 32 + tx;
    int y = blockIdx.y * 32 + ty;
    #pragma unroll
    for (int j = 0; j < 32; j += 8)
        tile[ty + j][tx] = in[(size_t)(y + j) * N + x];
    __syncthreads();
    int x2 = blockIdx.y * 32 + tx;
    int y2 = blockIdx.x * 32 + ty;
    #pragma unroll
    for (int j = 0; j < 32; j += 8)
        out[(size_t)(y2 + j) * K + x2] = tf32r(tile[tx][ty + j]);
}

__global__ __launch_bounds__(256) void wbc_kernel(
    const float* __restrict__ WB, const float* __restrict__ WC)
{   // rows 2048..2079 of g_WcatT: W_B^T then W_C^T
    int idx = blockIdx.x * 256 + threadIdx.x;     // 32*2048
    int j = idx >> 11, k = idx & 2047;
    float v = (j < 16) ? WB[(size_t)k*STATE + j] : WC[(size_t)k*STATE + (j - 16)];
    g_WcatT[(size_t)(2048 + j) * INNER + k] = tf32r(v);
}

__global__ __launch_bounds__(256) void zerocat_kernel()
{   // rows 2080..2175 of g_WcatT = 0
    int idx = blockIdx.x * 256 + threadIdx.x;     // 96*2048/4
    ((float4*)(g_WcatT + (size_t)2080 * INNER))[idx] = make_float4(0.f,0.f,0.f,0.f);
}

// ---------------------------------------------------------------- LayerNorm
__global__ __launch_bounds__(256) void ln_kernel(
    const float* __restrict__ x, const float* __restrict__ g,
    const float* __restrict__ bt)
{
    int r = blockIdx.x, t = threadIdx.x;
    float4 v = *(const float4*)(x + (size_t)r*HIDDEN + t*4);
    float s  = v.x + v.y + v.z + v.w;
    float s2 = v.x*v.x + v.y*v.y + v.z*v.z + v.w*v.w;
    #pragma unroll
    for (int off = 16; off > 0; off >>= 1) {
        s  += __shfl_xor_sync(0xffffffffu, s,  off);
        s2 += __shfl_xor_sync(0xffffffffu, s2, off);
    }
    __shared__ float a1[8], a2[8];
    if ((t & 31) == 0) { a1[t >> 5] = s; a2[t >> 5] = s2; }
    __syncthreads();
    float ts = 0.f, ts2 = 0.f;
    #pragma unroll
    for (int i = 0; i < 8; i++) { ts += a1[i]; ts2 += a2[i]; }
    float mu   = ts * (1.f / HIDDEN);
    float var  = fmaf(ts2, 1.f / HIDDEN, -mu * mu);
    float rstd = rsqrtf(var + 1e-5f);
    float4 g4 = *(const float4*)(g  + t*4);
    float4 b4 = *(const float4*)(bt + t*4);
    float4 ov;
    ov.x = (v.x - mu) * rstd * g4.x + b4.x;
    ov.y = (v.y - mu) * rstd * g4.y + b4.y;
    ov.z = (v.z - mu) * rstd * g4.z + b4.z;
    ov.w = (v.w - mu) * rstd * g4.w + b4.w;
    *(float4*)(g_xn + (size_t)r*HIDDEN + t*4) = ov;
}

// ----------------------------------------------- depthwise conv (k=3) + SiLU
__global__ __launch_bounds__(256) void conv_kernel(
    const float* __restrict__ cw, const float* __restrict__ cb)
{
    int idx = blockIdx.x * 256 + threadIdx.x;
    int d4 = idx & 511;
    int r  = idx >> 9;
    int l  = r & (SEQ - 1);
    const float* base = g_xz + (size_t)r*(2*INNER) + d4*4;
    float4 zero = make_float4(0.f, 0.f, 0.f, 0.f);
    float4 xm = (l > 0)       ? *(const float4*)(base - 2*INNER) : zero;
    float4 xc = *(const float4*)(base);
    float4 xp = (l < SEQ - 1) ? *(const float4*)(base + 2*INNER) : zero;
    const float4* cwp = (const float4*)(cw + d4*12);
    float4 t0 = cwp[0], t1 = cwp[1], t2 = cwp[2];
    float4 b4 = *(const float4*)(cb + d4*4);
    float o0 = t0.x*xm.x + t0.y*xc.x + t0.z*xp.x + b4.x;
    float o1 = t0.w*xm.y + t1.x*xc.y + t1.y*xp.y + b4.y;
    float o2 = t1.z*xm.z + t1.w*xc.z + t2.x*xp.z + b4.z;
    float o3 = t2.y*xm.w + t2.z*xc.w + t2.w*xp.w + b4.w;
    o0 *= __fdividef(1.f, 1.f + __expf(-o0));
    o1 *= __fdividef(1.f, 1.f + __expf(-o1));
    o2 *= __fdividef(1.f, 1.f + __expf(-o2));
    o3 *= __fdividef(1.f, 1.f + __expf(-o3));
    *(float4*)(g_xb + (size_t)r*INNER + d4*4) = make_float4(o0, o1, o2, o3);
}

// ---------------------------- selective scan + gating -----------------------
// block = 128 threads: 16 d-channels x 8 state-pairs. 512 blocks (4 b x 128).
// cp.async double-buffered tiles of 16 timesteps.
__global__ __launch_bounds__(128) void scan_kernel(
    const float* __restrict__ A_log, const float* __restrict__ Dp)
{
    __shared__ float s_dt[2][16][16];
    __shared__ float s_x [2][16][16];
    __shared__ float s_z [2][16][16];
    __shared__ float s_bc[2][16][32];
    __shared__ float s_y [16][16];

    int tid = threadIdx.x;
    int b  = blockIdx.x >> 7;
    int d0 = (blockIdx.x & 127) * 16;
    int q  = tid & 7, dl = tid >> 3;
    int d  = d0 + dl;

    float a0 = -__expf(A_log[d*STATE + 2*q]);
    float a1 = -__expf(A_log[d*STATE + 2*q + 1]);
    float Dd = Dp[d];
    size_t tokbase = (size_t)b * SEQ;

    uint32_t u_dt = (uint32_t)__cvta_generic_to_shared(&s_dt[0][0][0]);
    uint32_t u_x  = (uint32_t)__cvta_generic_to_shared(&s_x [0][0][0]);
    uint32_t u_z  = (uint32_t)__cvta_generic_to_shared(&s_z [0][0][0]);
    uint32_t u_bc = (uint32_t)__cvta_generic_to_shared(&s_bc[0][0][0]);

    auto stage = [&](int s) {
        int l0 = s * 16, buf = s & 1;
        #pragma unroll
        for (int ii = tid; ii < 320; ii += 128) {
            if (ii < 192) {
                int arr = ii >> 6, e = ii & 63;
                int rowi = e >> 2, c4 = e & 3;
                size_t tok = tokbase + l0 + rowi;
                uint32_t doff = (uint32_t)((rowi*16 + c4*4) * 4) + buf*1024;
                if (arr == 0)
                    cp16(u_dt + doff, g_dtbc + tok*NCAT + d0 + c4*4);
                else if (arr == 1)
                    cp16(u_x + doff, g_xb + tok*INNER + d0 + c4*4);
                else
                    cp16(u_z + doff, g_xz + tok*(2*INNER) + INNER + d0 + c4*4);
            } else {
                int e = ii - 192;
                int rowi = e >> 3, c8 = e & 7;
                size_t tok = tokbase + l0 + rowi;
                cp16(u_bc + buf*2048 + (uint32_t)((rowi*32 + c8*4) * 4),
                     g_dtbc + tok*NCAT + 2048 + c8*4);
            }
        }
    };

    stage(0); cp_commit();

    float h0 = 0.f, h1 = 0.f;
    for (int s = 0; s < SEQ/16; s++) {
        if (s + 1 < SEQ/16) { stage(s + 1); cp_commit(); cp_wait<1>(); }
        else cp_wait<0>();
        __syncthreads();

        int buf = s & 1;
        #pragma unroll
        for (int i = 0; i < 16; i++) {
            float dtc = s_dt[buf][i][dl];
            float xc  = s_x [buf][i][dl];
            float2 Bv = *(const float2*)&s_bc[buf][i][2*q];
            float2 Cv = *(const float2*)&s_bc[buf][i][16 + 2*q];
            float e0 = __expf(dtc * a0);
            float e1 = __expf(dtc * a1);
            float dx = dtc * xc;
            h0 = fmaf(e0, h0, dx * Bv.x);
            h1 = fmaf(e1, h1, dx * Bv.y);
            float p = fmaf(h1, Cv.y, h0 * Cv.x);
            p += __shfl_xor_sync(0xffffffffu, p, 1);
            p += __shfl_xor_sync(0xffffffffu, p, 2);
            p += __shfl_xor_sync(0xffffffffu, p, 4);
            if (q == 0) {
                float zz  = s_z[buf][i][dl];
                float sil = zz * __fdividef(1.f, 1.f + __expf(-zz));
                s_y[i][dl] = fmaf(Dd, xc, p) * sil;
            }
        }
        __syncthreads();
        if (tid < 64) {
            int rowi = tid >> 2, c4 = tid & 3;
            float4 v = *(float4*)&s_y[rowi][c4*4];
            *(float4*)(g_y + (tokbase + s*16 + rowi)*INNER + d0 + c4*4) = v;
        }
    }
}

// ------------------------------------------------------------------- launch
extern "C" void kernel_launch(void* const* d_in, const int* in_sizes, int n_in,
                              void* d_out, int out_size)
{
    const float* x    = (const float*)d_in[0];
    const float* ns   = (const float*)d_in[1];
    const float* nb   = (const float*)d_in[2];
    const float* Win  = (const float*)d_in[3];
    const float* cw   = (const float*)d_in[4];
    const float* cb   = (const float*)d_in[5];
    const float* Wdt  = (const float*)d_in[6];
    const float* bdt  = (const float*)d_in[7];
    const float* Alog = (const float*)d_in[8];
    const float* Dp   = (const float*)d_in[9];
    const float* WB   = (const float*)d_in[10];
    const float* WC   = (const float*)d_in[11];
    const float* Wout = (const float*)d_in[12];
    float* out = (float*)d_out;

    void *p_xn, *p_xz, *p_xb, *p_dtbc, *p_y, *p_wint, *p_wcatt, *p_woutt;
    cudaGetSymbolAddress(&p_xn,   g_xn);
    cudaGetSymbolAddress(&p_xz,   g_xz);
    cudaGetSymbolAddress(&p_xb,   g_xb);
    cudaGetSymbolAddress(&p_dtbc, g_dtbc);
    cudaGetSymbolAddress(&p_y,    g_y);
    cudaGetSymbolAddress(&p_wint,  g_WinT);
    cudaGetSymbolAddress(&p_wcatt, g_WcatT);
    cudaGetSymbolAddress(&p_woutt, g_WoutT);
    float* xn   = (float*)p_xn;    float* xz = (float*)p_xz;
    float* xb   = (float*)p_xb;    float* dtbc = (float*)p_dtbc;
    float* yv   = (float*)p_y;
    float* WinT  = (float*)p_wint;
    float* WcatT = (float*)p_wcatt;
    float* WoutT = (float*)p_woutt;

    // 0) weight prep
    transpose_kernel<<<dim3(2*INNER/32, HIDDEN/32), dim3(32,8)>>>(Win,  WinT,  HIDDEN, 2*INNER);
    transpose_kernel<<<dim3(INNER/32,   INNER/32),  dim3(32,8)>>>(Wdt,  WcatT, INNER,  INNER);
    wbc_kernel<<<(32*2048)/256, 256>>>(WB, WC);
    zerocat_kernel<<<(96*2048/4)/256, 256>>>();
    transpose_kernel<<<dim3(HIDDEN/32,  INNER/32),  dim3(32,8)>>>(Wout, WoutT, INNER,  HIDDEN);
    // 1) LayerNorm
    ln_kernel<<<TOK, 256>>>(x, ns, nb);
    // 2) xz = xn @ W_in
    gemm_mma<0><<<dim3(2*INNER/128, TOK/128), 128>>>(
        xn, WinT, xz, TOK, 2*INNER, HIDDEN, nullptr, nullptr);
    // 3) conv + SiLU
    conv_kernel<<<(TOK*INNER/4)/256, 256>>>(cw, cb);
    // 4) [dt | B | C] = xb @ Wcat  (softplus on dt cols)
    gemm_mma<1><<<dim3(NCAT/128, TOK/128), 128>>>(
        xb, WcatT, dtbc, TOK, NCAT, INNER, bdt, nullptr);
    // 5) selective scan + gating
    scan_kernel<<<512, 128>>>(Alog, Dp);
    // 6) out = x + y @ W_out
    gemm_mma<2><<<dim3(HIDDEN/128, TOK/128), 128>>>(
        yv, WoutT, out, TOK, HIDDEN, INNER, nullptr, x);
}

// round 9
// speedup vs baseline: 3.0212x; 1.0034x over previous
#include <cuda_runtime.h>
#include <cstdint>
#include <math.h>

#define HIDDEN 1024
#define INNER  2048
#define STATE  16
#define BATCH  4
#define SEQ    2048
#define TOK    (BATCH*SEQ)   // 8192
#define NCAT   2304          // 2048 dt | 16 B | 16 C | 224 pad (9 tiles of 256)

// ---------------- scratch (static device globals) ---------------------------
__device__ float g_xn[TOK*HIDDEN];
__device__ float g_xz[TOK*2*INNER];       // [xb_raw | z]
__device__ float g_xb[TOK*INNER];
__device__ float g_dtbc[TOK*NCAT];        // [softplus(dt)(2048) | B(16) | C(16) | pad]
__device__ float g_y [TOK*INNER];
__device__ float g_WinT [2*INNER*HIDDEN];
__device__ float g_WcatT[NCAT*INNER];     // [WdtT ; WB^T ; WC^T ; zeros]
__device__ float g_WoutT[HIDDEN*INNER];

// ============================== helpers =====================================
__device__ __forceinline__ float tf32r(float x) {
    float r; asm("cvt.rna.tf32.f32 %0, %1;" : "=f"(r) : "f"(x)); return r;
}
__device__ __forceinline__ void cp16(uint32_t s, const void* g) {
    asm volatile("cp.async.cg.shared.global [%0], [%1], 16;" :: "r"(s), "l"(g));
}
__device__ __forceinline__ void cp_commit() {
    asm volatile("cp.async.commit_group;" ::: "memory");
}
template<int N> __device__ __forceinline__ void cp_wait() {
    asm volatile("cp.async.wait_group %0;" :: "n"(N) : "memory");
}
__device__ __forceinline__ void mma_tf32(float* d, const uint32_t* a, const uint32_t* b) {
    asm volatile("mma.sync.aligned.m16n8k8.row.col.f32.tf32.tf32.f32 "
                 "{%0,%1,%2,%3},{%4,%5,%6,%7},{%8,%9},{%0,%1,%2,%3};"
                 : "+f"(d[0]), "+f"(d[1]), "+f"(d[2]), "+f"(d[3])
                 : "r"(a[0]), "r"(a[1]), "r"(a[2]), "r"(a[3]), "r"(b[0]), "r"(b[1]));
}
__device__ __forceinline__ float softplus_f(float v) {
    return fmaxf(v, 0.f) + __logf(1.f + __expf(-fabsf(v)));
}

// ====================== tf32 mma.sync GEMM ==================================
// C[M,N] = A[M,K] @ Bt[N,K]^T. BM=128, BN=256, BK=16, 256 threads (2x4 warps,
// 64x64 warp tiles), 4-stage cp.async pipeline, dynamic smem.
// EPI: 0 plain, 1 mixed softplus(dt)|raw(bc), 2 +residual
#define PAD 20
#define STAGES 4
#define A_STAGE_B (128*PAD*4)               // 10240 B
#define B_STAGE_B (256*PAD*4)               // 20480 B
#define GSMEM_BYTES (STAGES*(A_STAGE_B + B_STAGE_B))   // 122880 B

template<int EPI>
__global__ __launch_bounds__(256) void gemm_mma(
    const float* __restrict__ A, const float* __restrict__ Bt, float* __restrict__ C,
    int M, int N, int K,
    const float* __restrict__ bias, const float* __restrict__ resid)
{
    extern __shared__ float smem[];
    float* Abase = smem;                           // STAGES x 128 x PAD
    float* Bbase = smem + STAGES*128*PAD;          // STAGES x 256 x PAD

    int tid = threadIdx.x, lane = tid & 31, wid = tid >> 5;
    int wm = wid >> 2, wn = wid & 3;               // 2 x 4 warp grid
    int m0 = blockIdx.y * 128, n0 = blockIdx.x * 256;

    uint32_t uA = (uint32_t)__cvta_generic_to_shared(Abase);
    uint32_t uB = (uint32_t)__cvta_generic_to_shared(Bbase);

    // staging map: f4 index e -> row = e>>2, c4 = e&3
    const float* Agm = A  + (size_t)m0 * K;
    const float* Bgm = Bt + (size_t)n0 * K;

    int ns = K >> 4;

    auto load_stage = [&](int s) {
        int buf = s & (STAGES - 1);
        const float* Ak = Agm + s * 16;
        const float* Bk = Bgm + s * 16;
        uint32_t ab = uA + buf * A_STAGE_B;
        uint32_t bb = uB + buf * B_STAGE_B;
        #pragma unroll
        for (int i = 0; i < 2; i++) {              // A: 512 f4
            int e = tid + i * 256;
            int row = e >> 2, c4 = e & 3;
            cp16(ab + (uint32_t)((row*PAD + c4*4) * 4), Ak + (size_t)row * K + c4*4);
        }
        #pragma unroll
        for (int i = 0; i < 4; i++) {              // B: 1024 f4
            int e = tid + i * 256;
            int row = e >> 2, c4 = e & 3;
            cp16(bb + (uint32_t)((row*PAD + c4*4) * 4), Bk + (size_t)row * K + c4*4);
        }
        cp_commit();
    };

    load_stage(0); load_stage(1); load_stage(2);

    float acc[4][8][4] = {};
    int r = lane >> 2, c = lane & 3;

    for (int s = 0; s < ns; s++) {
        cp_wait<STAGES - 2>();
        __syncthreads();
        if (s + STAGES - 1 < ns) load_stage(s + STAGES - 1);

        int buf = s & (STAGES - 1);
        const float* Ab = Abase + buf * 128*PAD;
        const float* Bb = Bbase + buf * 256*PAD;
        #pragma unroll
        for (int ks = 0; ks < 2; ks++) {
            uint32_t af[4][4], bf[8][2];
            #pragma unroll
            for (int am = 0; am < 4; am++) {
                const float* p = Ab + (wm*64 + am*16 + r) * PAD + ks*8 + c;
                af[am][0] = __float_as_uint(p[0]);
                af[am][1] = __float_as_uint(p[8*PAD]);
                af[am][2] = __float_as_uint(p[4]);
                af[am][3] = __float_as_uint(p[8*PAD + 4]);
            }
            #pragma unroll
            for (int bn = 0; bn < 8; bn++) {
                const float* p = Bb + (wn*64 + bn*8 + r) * PAD + ks*8 + c;
                bf[bn][0] = __float_as_uint(p[0]);
                bf[bn][1] = __float_as_uint(p[4]);
            }
            #pragma unroll
            for (int am = 0; am < 4; am++)
                #pragma unroll
                for (int bn = 0; bn < 8; bn++)
                    mma_tf32(acc[am][bn], af[am], bf[bn]);
        }
    }

    // ------------------------------- epilogue -------------------------------
    #pragma unroll
    for (int am = 0; am < 4; am++) {
        int row0 = m0 + wm*64 + am*16 + r;
        #pragma unroll
        for (int bn = 0; bn < 8; bn++) {
            int col = n0 + wn*64 + bn*8 + 2*c;
            #pragma unroll
            for (int h = 0; h < 2; h++) {
                int row = row0 + h*8;
                float v0 = acc[am][bn][h*2 + 0];
                float v1 = acc[am][bn][h*2 + 1];
                if (EPI == 1) {
                    if (col < 2048) {
                        v0 = softplus_f(v0 + bias[col]);
                        v1 = softplus_f(v1 + bias[col + 1]);
                    }
                } else if (EPI == 2) {
                    const float* rp = resid + (size_t)row * N + col;
                    v0 += rp[0]; v1 += rp[1];
                }
                *(float2*)(C + (size_t)row * N + col) = make_float2(v0, v1);
            }
        }
    }
}

// ------------------------------- weight prep --------------------------------
__global__ __launch_bounds__(256) void transpose_kernel(
    const float* __restrict__ in, float* __restrict__ out, int K, int N)
{   // in [K,N] -> out [N,K], tf32-rounded
    __shared__ float tile[32][33];
    int tx = threadIdx.x, ty = threadIdx.y;
    int x = blockIdx.x * 32 + tx;
    int y = blockIdx.y * 32 + ty;
    #pragma unroll
    for (int j = 0; j < 32; j += 8)
        tile[ty + j][tx] = in[(size_t)(y + j) * N + x];
    __syncthreads();
    int x2 = blockIdx.y * 32 + tx;
    int y2 = blockIdx.x * 32 + ty;
    #pragma unroll
    for (int j = 0; j < 32; j += 8)
        out[(size_t)(y2 + j) * K + x2] = tf32r(tile[tx][ty + j]);
}

__global__ __launch_bounds__(256) void wbc_kernel(
    const float* __restrict__ WB, const float* __restrict__ WC)
{   // rows 2048..2303 of g_WcatT: W_B^T, W_C^T, then zeros
    int idx = blockIdx.x * 256 + threadIdx.x;     // 256*2048
    int j = idx >> 11, k = idx & 2047;
    float v = (j < 16) ? WB[(size_t)k*STATE + j]
            : (j < 32) ? WC[(size_t)k*STATE + (j - 16)]
            : 0.f;
    g_WcatT[(size_t)(2048 + j) * INNER + k] = tf32r(v);
}

// ---------------------------------------------------------------- LayerNorm
__global__ __launch_bounds__(256) void ln_kernel(
    const float* __restrict__ x, const float* __restrict__ g,
    const float* __restrict__ bt)
{
    int r = blockIdx.x, t = threadIdx.x;
    float4 v = *(const float4*)(x + (size_t)r*HIDDEN + t*4);
    float s  = v.x + v.y + v.z + v.w;
    float s2 = v.x*v.x + v.y*v.y + v.z*v.z + v.w*v.w;
    #pragma unroll
    for (int off = 16; off > 0; off >>= 1) {
        s  += __shfl_xor_sync(0xffffffffu, s,  off);
        s2 += __shfl_xor_sync(0xffffffffu, s2, off);
    }
    __shared__ float a1[8], a2[8];
    if ((t & 31) == 0) { a1[t >> 5] = s; a2[t >> 5] = s2; }
    __syncthreads();
    float ts = 0.f, ts2 = 0.f;
    #pragma unroll
    for (int i = 0; i < 8; i++) { ts += a1[i]; ts2 += a2[i]; }
    float mu   = ts * (1.f / HIDDEN);
    float var  = fmaf(ts2, 1.f / HIDDEN, -mu * mu);
    float rstd = rsqrtf(var + 1e-5f);
    float4 g4 = *(const float4*)(g  + t*4);
    float4 b4 = *(const float4*)(bt + t*4);
    float4 ov;
    ov.x = (v.x - mu) * rstd * g4.x + b4.x;
    ov.y = (v.y - mu) * rstd * g4.y + b4.y;
    ov.z = (v.z - mu) * rstd * g4.z + b4.z;
    ov.w = (v.w - mu) * rstd * g4.w + b4.w;
    *(float4*)(g_xn + (size_t)r*HIDDEN + t*4) = ov;
}

// ----------------------------------------------- depthwise conv (k=3) + SiLU
__global__ __launch_bounds__(256) void conv_kernel(
    const float* __restrict__ cw, const float* __restrict__ cb)
{
    int idx = blockIdx.x * 256 + threadIdx.x;
    int d4 = idx & 511;
    int r  = idx >> 9;
    int l  = r & (SEQ - 1);
    const float* base = g_xz + (size_t)r*(2*INNER) + d4*4;
    float4 zero = make_float4(0.f, 0.f, 0.f, 0.f);
    float4 xm = (l > 0)       ? *(const float4*)(base - 2*INNER) : zero;
    float4 xc = *(const float4*)(base);
    float4 xp = (l < SEQ - 1) ? *(const float4*)(base + 2*INNER) : zero;
    const float4* cwp = (const float4*)(cw + d4*12);
    float4 t0 = cwp[0], t1 = cwp[1], t2 = cwp[2];
    float4 b4 = *(const float4*)(cb + d4*4);
    float o0 = t0.x*xm.x + t0.y*xc.x + t0.z*xp.x + b4.x;
    float o1 = t0.w*xm.y + t1.x*xc.y + t1.y*xp.y + b4.y;
    float o2 = t1.z*xm.z + t1.w*xc.z + t2.x*xp.z + b4.z;
    float o3 = t2.y*xm.w + t2.z*xc.w + t2.w*xp.w + b4.w;
    o0 *= __fdividef(1.f, 1.f + __expf(-o0));
    o1 *= __fdividef(1.f, 1.f + __expf(-o1));
    o2 *= __fdividef(1.f, 1.f + __expf(-o2));
    o3 *= __fdividef(1.f, 1.f + __expf(-o3));
    *(float4*)(g_xb + (size_t)r*INNER + d4*4) = make_float4(o0, o1, o2, o3);
}

// ---------------------------- selective scan + gating -----------------------
// block = 128 threads: 16 d-channels x 8 state-pairs; cp.async tiles of 16 steps
__global__ __launch_bounds__(128) void scan_kernel(
    const float* __restrict__ A_log, const float* __restrict__ Dp)
{
    __shared__ float s_dt[2][16][16];
    __shared__ float s_x [2][16][16];
    __shared__ float s_z [2][16][16];
    __shared__ float s_bc[2][16][32];
    __shared__ float s_y [16][16];

    int tid = threadIdx.x;
    int b  = blockIdx.x >> 7;
    int d0 = (blockIdx.x & 127) * 16;
    int q  = tid & 7, dl = tid >> 3;
    int d  = d0 + dl;

    float a0 = -__expf(A_log[d*STATE + 2*q]);
    float a1 = -__expf(A_log[d*STATE + 2*q + 1]);
    float Dd = Dp[d];
    size_t tokbase = (size_t)b * SEQ;

    uint32_t u_dt = (uint32_t)__cvta_generic_to_shared(&s_dt[0][0][0]);
    uint32_t u_x  = (uint32_t)__cvta_generic_to_shared(&s_x [0][0][0]);
    uint32_t u_z  = (uint32_t)__cvta_generic_to_shared(&s_z [0][0][0]);
    uint32_t u_bc = (uint32_t)__cvta_generic_to_shared(&s_bc[0][0][0]);

    auto stage = [&](int s) {
        int l0 = s * 16, buf = s & 1;
        #pragma unroll
        for (int ii = tid; ii < 320; ii += 128) {
            if (ii < 192) {
                int arr = ii >> 6, e = ii & 63;
                int rowi = e >> 2, c4 = e & 3;
                size_t tok = tokbase + l0 + rowi;
                uint32_t doff = (uint32_t)((rowi*16 + c4*4) * 4) + buf*1024;
                if (arr == 0)
                    cp16(u_dt + doff, g_dtbc + tok*NCAT + d0 + c4*4);
                else if (arr == 1)
                    cp16(u_x + doff, g_xb + tok*INNER + d0 + c4*4);
                else
                    cp16(u_z + doff, g_xz + tok*(2*INNER) + INNER + d0 + c4*4);
            } else {
                int e = ii - 192;
                int rowi = e >> 3, c8 = e & 7;
                size_t tok = tokbase + l0 + rowi;
                cp16(u_bc + buf*2048 + (uint32_t)((rowi*32 + c8*4) * 4),
                     g_dtbc + tok*NCAT + 2048 + c8*4);
            }
        }
    };

    stage(0); cp_commit();

    float h0 = 0.f, h1 = 0.f;
    for (int s = 0; s < SEQ/16; s++) {
        if (s + 1 < SEQ/16) { stage(s + 1); cp_commit(); cp_wait<1>(); }
        else cp_wait<0>();
        __syncthreads();

        int buf = s & 1;
        #pragma unroll
        for (int i = 0; i < 16; i++) {
            float dtc = s_dt[buf][i][dl];
            float xc  = s_x [buf][i][dl];
            float2 Bv = *(const float2*)&s_bc[buf][i][2*q];
            float2 Cv = *(const float2*)&s_bc[buf][i][16 + 2*q];
            float e0 = __expf(dtc * a0);
            float e1 = __expf(dtc * a1);
            float dx = dtc * xc;
            h0 = fmaf(e0, h0, dx * Bv.x);
            h1 = fmaf(e1, h1, dx * Bv.y);
            float p = fmaf(h1, Cv.y, h0 * Cv.x);
            p += __shfl_xor_sync(0xffffffffu, p, 1);
            p += __shfl_xor_sync(0xffffffffu, p, 2);
            p += __shfl_xor_sync(0xffffffffu, p, 4);
            if (q == 0) {
                float zz  = s_z[buf][i][dl];
                float sil = zz * __fdividef(1.f, 1.f + __expf(-zz));
                s_y[i][dl] = fmaf(Dd, xc, p) * sil;
            }
        }
        __syncthreads();
        if (tid < 64) {
            int rowi = tid >> 2, c4 = tid & 3;
            float4 v = *(float4*)&s_y[rowi][c4*4];
            *(float4*)(g_y + (tokbase + s*16 + rowi)*INNER + d0 + c4*4) = v;
        }
    }
}

// ------------------------------------------------------------------- launch
extern "C" void kernel_launch(void* const* d_in, const int* in_sizes, int n_in,
                              void* d_out, int out_size)
{
    const float* x    = (const float*)d_in[0];
    const float* ns   = (const float*)d_in[1];
    const float* nb   = (const float*)d_in[2];
    const float* Win  = (const float*)d_in[3];
    const float* cw   = (const float*)d_in[4];
    const float* cb   = (const float*)d_in[5];
    const float* Wdt  = (const float*)d_in[6];
    const float* bdt  = (const float*)d_in[7];
    const float* Alog = (const float*)d_in[8];
    const float* Dp   = (const float*)d_in[9];
    const float* WB   = (const float*)d_in[10];
    const float* WC   = (const float*)d_in[11];
    const float* Wout = (const float*)d_in[12];
    float* out = (float*)d_out;

    void *p_xn, *p_xz, *p_xb, *p_dtbc, *p_y, *p_wint, *p_wcatt, *p_woutt;
    cudaGetSymbolAddress(&p_xn,   g_xn);
    cudaGetSymbolAddress(&p_xz,   g_xz);
    cudaGetSymbolAddress(&p_xb,   g_xb);
    cudaGetSymbolAddress(&p_dtbc, g_dtbc);
    cudaGetSymbolAddress(&p_y,    g_y);
    cudaGetSymbolAddress(&p_wint,  g_WinT);
    cudaGetSymbolAddress(&p_wcatt, g_WcatT);
    cudaGetSymbolAddress(&p_woutt, g_WoutT);
    float* xn   = (float*)p_xn;    float* xz = (float*)p_xz;
    float* xb   = (float*)p_xb;    float* dtbc = (float*)p_dtbc;
    float* yv   = (float*)p_y;
    float* WinT  = (float*)p_wint;
    float* WcatT = (float*)p_wcatt;
    float* WoutT = (float*)p_woutt;

    cudaFuncSetAttribute(gemm_mma<0>, cudaFuncAttributeMaxDynamicSharedMemorySize, GSMEM_BYTES);
    cudaFuncSetAttribute(gemm_mma<1>, cudaFuncAttributeMaxDynamicSharedMemorySize, GSMEM_BYTES);
    cudaFuncSetAttribute(gemm_mma<2>, cudaFuncAttributeMaxDynamicSharedMemorySize, GSMEM_BYTES);

    // 0) weight prep (4 launches) + ln (5th) -> gemm<0> is 6th for ncu -s 5
    transpose_kernel<<<dim3(2*INNER/32, HIDDEN/32), dim3(32,8)>>>(Win,  WinT,  HIDDEN, 2*INNER);
    transpose_kernel<<<dim3(INNER/32,   INNER/32),  dim3(32,8)>>>(Wdt,  WcatT, INNER,  INNER);
    transpose_kernel<<<dim3(HIDDEN/32,  INNER/32),  dim3(32,8)>>>(Wout, WoutT, INNER,  HIDDEN);
    wbc_kernel<<<(256*2048)/256, 256>>>(WB, WC);
    // 1) LayerNorm
    ln_kernel<<<TOK, 256>>>(x, ns, nb);
    // 2) xz = xn @ W_in
    gemm_mma<0><<<dim3(2*INNER/256, TOK/128), 256, GSMEM_BYTES>>>(
        xn, WinT, xz, TOK, 2*INNER, HIDDEN, nullptr, nullptr);
    // 3) conv + SiLU
    conv_kernel<<<(TOK*INNER/4)/256, 256>>>(cw, cb);
    // 4) [dt | B | C] = xb @ Wcat  (softplus on dt cols)
    gemm_mma<1><<<dim3(NCAT/256, TOK/128), 256, GSMEM_BYTES>>>(
        xb, WcatT, dtbc, TOK, NCAT, INNER, bdt, nullptr);
    // 5) selective scan + gating
    scan_kernel<<<512, 128>>>(Alog, Dp);
    // 6) out = x + y @ W_out
    gemm_mma<2><<<dim3(HIDDEN/256, TOK/128), 256, GSMEM_BYTES>>>(
        yv, WoutT, out, TOK, HIDDEN, INNER, nullptr, x);
}

// round 10
// speedup vs baseline: 4.1923x; 1.3877x over previous
#include <cuda_runtime.h>
#include <cuda_bf16.h>
#include <cstdint>
#include <math.h>

#define HIDDEN 1024
#define INNER  2048
#define STATE  16
#define BATCH  4
#define SEQ    2048
#define TOK    (BATCH*SEQ)   // 8192
#define NCAT   2304          // 2048 dt | 16 B | 16 C | 224 pad (9 tiles of 256)

// ---------------- scratch (static device globals) ---------------------------
__device__ __nv_bfloat16 g_xnh[TOK*HIDDEN];      // ln output (bf16, GEMM1 A)
__device__ float g_xz[TOK*2*INNER];              // GEMM1 out [xb_raw | z] fp32
__device__ float g_xb[TOK*INNER];                // conv+silu fp32 (scan)
__device__ __nv_bfloat16 g_xbh[TOK*INNER];       // conv+silu bf16 (GEMM2 A)
__device__ float g_dtbc[TOK*NCAT];               // [softplus(dt) | B | C | pad]
__device__ float g_y [TOK*INNER];                // gated SSM output (GEMM3 A)
__device__ __nv_bfloat16 g_WinTh [2*INNER*HIDDEN];
__device__ __nv_bfloat16 g_WcatTh[NCAT*INNER];
__device__ float g_WoutT[HIDDEN*INNER];

// ============================== helpers =====================================
__device__ __forceinline__ float tf32r(float x) {
    float r; asm("cvt.rna.tf32.f32 %0, %1;" : "=f"(r) : "f"(x)); return r;
}
__device__ __forceinline__ void cp16(uint32_t s, const void* g) {
    asm volatile("cp.async.cg.shared.global [%0], [%1], 16;" :: "r"(s), "l"(g));
}
__device__ __forceinline__ void cp_commit() {
    asm volatile("cp.async.commit_group;" ::: "memory");
}
template<int N> __device__ __forceinline__ void cp_wait() {
    asm volatile("cp.async.wait_group %0;" :: "n"(N) : "memory");
}
__device__ __forceinline__ void mma_tf32(float* d, const uint32_t* a, const uint32_t* b) {
    asm volatile("mma.sync.aligned.m16n8k8.row.col.f32.tf32.tf32.f32 "
                 "{%0,%1,%2,%3},{%4,%5,%6,%7},{%8,%9},{%0,%1,%2,%3};"
                 : "+f"(d[0]), "+f"(d[1]), "+f"(d[2]), "+f"(d[3])
                 : "r"(a[0]), "r"(a[1]), "r"(a[2]), "r"(a[3]), "r"(b[0]), "r"(b[1]));
}
__device__ __forceinline__ void mma_bf16(float* d, const uint32_t* a, const uint32_t* b) {
    asm volatile("mma.sync.aligned.m16n8k16.row.col.f32.bf16.bf16.f32 "
                 "{%0,%1,%2,%3},{%4,%5,%6,%7},{%8,%9},{%0,%1,%2,%3};"
                 : "+f"(d[0]), "+f"(d[1]), "+f"(d[2]), "+f"(d[3])
                 : "r"(a[0]), "r"(a[1]), "r"(a[2]), "r"(a[3]), "r"(b[0]), "r"(b[1]));
}
__device__ __forceinline__ float softplus_f(float v) {
    return fmaxf(v, 0.f) + __logf(1.f + __expf(-fabsf(v)));
}

// ====================== bf16 mma.sync GEMM ==================================
// C[M,N] = A[M,K] @ Bt[N,K]^T, bf16 inputs, fp32 acc/output.
// BM=128, BN=256, BK=32, 256 threads (2x4 warps, 64x64 warp tiles),
// 4-stage cp.async pipeline. Rows padded to 40 bf16 (80 B) -> conflict-free.
// EPI: 0 plain, 1 mixed softplus(dt)|raw(bc)
#define PADH_B 80                             // bytes per smem row
#define AH_STAGE_B (128*PADH_B)               // 10240
#define BH_STAGE_B (256*PADH_B)               // 20480
#define GSMEMH (4*(AH_STAGE_B + BH_STAGE_B))  // 122880

template<int EPI>
__global__ __launch_bounds__(256) void gemm_bf16k(
    const __nv_bfloat16* __restrict__ A, const __nv_bfloat16* __restrict__ Bt,
    float* __restrict__ C, int M, int N, int K, const float* __restrict__ bias)
{
    extern __shared__ char smemc[];
    char* Abase = smemc;
    char* Bbase = smemc + 4*AH_STAGE_B;

    int tid = threadIdx.x, lane = tid & 31, wid = tid >> 5;
    int wm = wid >> 2, wn = wid & 3;
    int m0 = blockIdx.y * 128, n0 = blockIdx.x * 256;

    uint32_t uA = (uint32_t)__cvta_generic_to_shared(Abase);
    uint32_t uB = (uint32_t)__cvta_generic_to_shared(Bbase);

    const __nv_bfloat16* Agm = A  + (size_t)m0 * K;
    const __nv_bfloat16* Bgm = Bt + (size_t)n0 * K;

    int ns = K >> 5;                          // BK = 32

    auto load_stage = [&](int s) {
        int buf = s & 3;
        const __nv_bfloat16* Ak = Agm + s * 32;
        const __nv_bfloat16* Bk = Bgm + s * 32;
        uint32_t ab = uA + buf * AH_STAGE_B;
        uint32_t bb = uB + buf * BH_STAGE_B;
        #pragma unroll
        for (int i = 0; i < 2; i++) {         // A: 512 x 16B (128 rows x 64B)
            int e = tid + i * 256;
            int row = e >> 2, c4 = e & 3;
            cp16(ab + (uint32_t)(row*PADH_B + c4*16), Ak + (size_t)row * K + c4*8);
        }
        #pragma unroll
        for (int i = 0; i < 4; i++) {         // B: 1024 x 16B (256 rows x 64B)
            int e = tid + i * 256;
            int row = e >> 2, c4 = e & 3;
            cp16(bb + (uint32_t)(row*PADH_B + c4*16), Bk + (size_t)row * K + c4*8);
        }
        cp_commit();
    };

    load_stage(0); load_stage(1); load_stage(2);

    float acc[4][8][4] = {};
    int r = lane >> 2, c = lane & 3;

    for (int s = 0; s < ns; s++) {
        cp_wait<2>();
        __syncthreads();
        if (s + 3 < ns) load_stage(s + 3);

        int buf = s & 3;
        const char* Ab = Abase + buf * AH_STAGE_B;
        const char* Bb = Bbase + buf * BH_STAGE_B;
        #pragma unroll
        for (int ks = 0; ks < 2; ks++) {      // two k16 slices per stage
            uint32_t af[4][4], bf[8][2];
            #pragma unroll
            for (int am = 0; am < 4; am++) {
                const char* p = Ab + (wm*64 + am*16 + r) * PADH_B + ks*32 + c*4;
                af[am][0] = *(const uint32_t*)p;
                af[am][1] = *(const uint32_t*)(p + 8*PADH_B);
                af[am][2] = *(const uint32_t*)(p + 16);
                af[am][3] = *(const uint32_t*)(p + 8*PADH_B + 16);
            }
            #pragma unroll
            for (int bn = 0; bn < 8; bn++) {
                const char* p = Bb + (wn*64 + bn*8 + r) * PADH_B + ks*32 + c*4;
                bf[bn][0] = *(const uint32_t*)p;
                bf[bn][1] = *(const uint32_t*)(p + 16);
            }
            #pragma unroll
            for (int am = 0; am < 4; am++)
                #pragma unroll
                for (int bn = 0; bn < 8; bn++)
                    mma_bf16(acc[am][bn], af[am], bf[bn]);
        }
    }

    #pragma unroll
    for (int am = 0; am < 4; am++) {
        int row0 = m0 + wm*64 + am*16 + r;
        #pragma unroll
        for (int bn = 0; bn < 8; bn++) {
            int col = n0 + wn*64 + bn*8 + 2*c;
            #pragma unroll
            for (int h = 0; h < 2; h++) {
                int row = row0 + h*8;
                float v0 = acc[am][bn][h*2 + 0];
                float v1 = acc[am][bn][h*2 + 1];
                if (EPI == 1) {
                    if (col < 2048) {
                        v0 = softplus_f(v0 + bias[col]);
                        v1 = softplus_f(v1 + bias[col + 1]);
                    }
                }
                *(float2*)(C + (size_t)row * N + col) = make_float2(v0, v1);
            }
        }
    }
}

// ====================== tf32 mma.sync GEMM (output proj) ====================
#define PAD 20
#define A_STAGE_B (128*PAD*4)
#define B_STAGE_B (256*PAD*4)
#define GSMEM_T (4*(A_STAGE_B + B_STAGE_B))

__global__ __launch_bounds__(256) void gemm_tf32k(
    const float* __restrict__ A, const float* __restrict__ Bt, float* __restrict__ C,
    int M, int N, int K, const float* __restrict__ resid)
{
    extern __shared__ float smem[];
    float* Abase = smem;
    float* Bbase = smem + 4*128*PAD;

    int tid = threadIdx.x, lane = tid & 31, wid = tid >> 5;
    int wm = wid >> 2, wn = wid & 3;
    int m0 = blockIdx.y * 128, n0 = blockIdx.x * 256;

    uint32_t uA = (uint32_t)__cvta_generic_to_shared(Abase);
    uint32_t uB = (uint32_t)__cvta_generic_to_shared(Bbase);

    const float* Agm = A  + (size_t)m0 * K;
    const float* Bgm = Bt + (size_t)n0 * K;

    int ns = K >> 4;

    auto load_stage = [&](int s) {
        int buf = s & 3;
        const float* Ak = Agm + s * 16;
        const float* Bk = Bgm + s * 16;
        uint32_t ab = uA + buf * A_STAGE_B;
        uint32_t bb = uB + buf * B_STAGE_B;
        #pragma unroll
        for (int i = 0; i < 2; i++) {
            int e = tid + i * 256;
            int row = e >> 2, c4 = e & 3;
            cp16(ab + (uint32_t)((row*PAD + c4*4) * 4), Ak + (size_t)row * K + c4*4);
        }
        #pragma unroll
        for (int i = 0; i < 4; i++) {
            int e = tid + i * 256;
            int row = e >> 2, c4 = e & 3;
            cp16(bb + (uint32_t)((row*PAD + c4*4) * 4), Bk + (size_t)row * K + c4*4);
        }
        cp_commit();
    };

    load_stage(0); load_stage(1); load_stage(2);

    float acc[4][8][4] = {};
    int r = lane >> 2, c = lane & 3;

    for (int s = 0; s < ns; s++) {
        cp_wait<2>();
        __syncthreads();
        if (s + 3 < ns) load_stage(s + 3);

        int buf = s & 3;
        const float* Ab = Abase + buf * 128*PAD;
        const float* Bb = Bbase + buf * 256*PAD;
        #pragma unroll
        for (int ks = 0; ks < 2; ks++) {
            uint32_t af[4][4], bf[8][2];
            #pragma unroll
            for (int am = 0; am < 4; am++) {
                const float* p = Ab + (wm*64 + am*16 + r) * PAD + ks*8 + c;
                af[am][0] = __float_as_uint(p[0]);
                af[am][1] = __float_as_uint(p[8*PAD]);
                af[am][2] = __float_as_uint(p[4]);
                af[am][3] = __float_as_uint(p[8*PAD + 4]);
            }
            #pragma unroll
            for (int bn = 0; bn < 8; bn++) {
                const float* p = Bb + (wn*64 + bn*8 + r) * PAD + ks*8 + c;
                bf[bn][0] = __float_as_uint(p[0]);
                bf[bn][1] = __float_as_uint(p[4]);
            }
            #pragma unroll
            for (int am = 0; am < 4; am++)
                #pragma unroll
                for (int bn = 0; bn < 8; bn++)
                    mma_tf32(acc[am][bn], af[am], bf[bn]);
        }
    }

    #pragma unroll
    for (int am = 0; am < 4; am++) {
        int row0 = m0 + wm*64 + am*16 + r;
        #pragma unroll
        for (int bn = 0; bn < 8; bn++) {
            int col = n0 + wn*64 + bn*8 + 2*c;
            #pragma unroll
            for (int h = 0; h < 2; h++) {
                int row = row0 + h*8;
                const float* rp = resid + (size_t)row * N + col;
                float v0 = acc[am][bn][h*2 + 0] + rp[0];
                float v1 = acc[am][bn][h*2 + 1] + rp[1];
                *(float2*)(C + (size_t)row * N + col) = make_float2(v0, v1);
            }
        }
    }
}

// ------------------------------- weight prep --------------------------------
__global__ __launch_bounds__(256) void tr_bf16(
    const float* __restrict__ in, __nv_bfloat16* __restrict__ out, int K, int N)
{   // in [K,N] fp32 -> out [N,K] bf16
    __shared__ float tile[32][33];
    int tx = threadIdx.x, ty = threadIdx.y;
    int x = blockIdx.x * 32 + tx;
    int y = blockIdx.y * 32 + ty;
    #pragma unroll
    for (int j = 0; j < 32; j += 8)
        tile[ty + j][tx] = in[(size_t)(y + j) * N + x];
    __syncthreads();
    int x2 = blockIdx.y * 32 + tx;
    int y2 = blockIdx.x * 32 + ty;
    #pragma unroll
    for (int j = 0; j < 32; j += 8)
        out[(size_t)(y2 + j) * K + x2] = __float2bfloat16(tile[tx][ty + j]);
}

__global__ __launch_bounds__(256) void tr_tf32(
    const float* __restrict__ in, float* __restrict__ out, int K, int N)
{
    __shared__ float tile[32][33];
    int tx = threadIdx.x, ty = threadIdx.y;
    int x = blockIdx.x * 32 + tx;
    int y = blockIdx.y * 32 + ty;
    #pragma unroll
    for (int j = 0; j < 32; j += 8)
        tile[ty + j][tx] = in[(size_t)(y + j) * N + x];
    __syncthreads();
    int x2 = blockIdx.y * 32 + tx;
    int y2 = blockIdx.x * 32 + ty;
    #pragma unroll
    for (int j = 0; j < 32; j += 8)
        out[(size_t)(y2 + j) * K + x2] = tf32r(tile[tx][ty + j]);
}

__global__ __launch_bounds__(256) void wbc_kernel(
    const float* __restrict__ WB, const float* __restrict__ WC)
{   // rows 2048..2303 of g_WcatTh: W_B^T, W_C^T, zeros
    int idx = blockIdx.x * 256 + threadIdx.x;     // 256*2048
    int j = idx >> 11, k = idx & 2047;
    float v = (j < 16) ? WB[(size_t)k*STATE + j]
            : (j < 32) ? WC[(size_t)k*STATE + (j - 16)]
            : 0.f;
    g_WcatTh[(size_t)(2048 + j) * INNER + k] = __float2bfloat16(v);
}

// ---------------------------------------------------------------- LayerNorm
__global__ __launch_bounds__(256) void ln_kernel(
    const float* __restrict__ x, const float* __restrict__ g,
    const float* __restrict__ bt)
{
    int r = blockIdx.x, t = threadIdx.x;
    float4 v = *(const float4*)(x + (size_t)r*HIDDEN + t*4);
    float s  = v.x + v.y + v.z + v.w;
    float s2 = v.x*v.x + v.y*v.y + v.z*v.z + v.w*v.w;
    #pragma unroll
    for (int off = 16; off > 0; off >>= 1) {
        s  += __shfl_xor_sync(0xffffffffu, s,  off);
        s2 += __shfl_xor_sync(0xffffffffu, s2, off);
    }
    __shared__ float a1[8], a2[8];
    if ((t & 31) == 0) { a1[t >> 5] = s; a2[t >> 5] = s2; }
    __syncthreads();
    float ts = 0.f, ts2 = 0.f;
    #pragma unroll
    for (int i = 0; i < 8; i++) { ts += a1[i]; ts2 += a2[i]; }
    float mu   = ts * (1.f / HIDDEN);
    float var  = fmaf(ts2, 1.f / HIDDEN, -mu * mu);
    float rstd = rsqrtf(var + 1e-5f);
    float4 g4 = *(const float4*)(g  + t*4);
    float4 b4 = *(const float4*)(bt + t*4);
    float4 ov;
    ov.x = (v.x - mu) * rstd * g4.x + b4.x;
    ov.y = (v.y - mu) * rstd * g4.y + b4.y;
    ov.z = (v.z - mu) * rstd * g4.z + b4.z;
    ov.w = (v.w - mu) * rstd * g4.w + b4.w;
    union { __nv_bfloat162 h[2]; uint2 u; } pk;
    pk.h[0] = __floats2bfloat162_rn(ov.x, ov.y);
    pk.h[1] = __floats2bfloat162_rn(ov.z, ov.w);
    *(uint2*)(g_xnh + (size_t)r*HIDDEN + t*4) = pk.u;
}

// ----------------------------------------------- depthwise conv (k=3) + SiLU
__global__ __launch_bounds__(256) void conv_kernel(
    const float* __restrict__ cw, const float* __restrict__ cb)
{
    int idx = blockIdx.x * 256 + threadIdx.x;
    int d4 = idx & 511;
    int r  = idx >> 9;
    int l  = r & (SEQ - 1);
    const float* base = g_xz + (size_t)r*(2*INNER) + d4*4;
    float4 zero = make_float4(0.f, 0.f, 0.f, 0.f);
    float4 xm = (l > 0)       ? *(const float4*)(base - 2*INNER) : zero;
    float4 xc = *(const float4*)(base);
    float4 xp = (l < SEQ - 1) ? *(const float4*)(base + 2*INNER) : zero;
    const float4* cwp = (const float4*)(cw + d4*12);
    float4 t0 = cwp[0], t1 = cwp[1], t2 = cwp[2];
    float4 b4 = *(const float4*)(cb + d4*4);
    float o0 = t0.x*xm.x + t0.y*xc.x + t0.z*xp.x + b4.x;
    float o1 = t0.w*xm.y + t1.x*xc.y + t1.y*xp.y + b4.y;
    float o2 = t1.z*xm.z + t1.w*xc.z + t2.x*xp.z + b4.z;
    float o3 = t2.y*xm.w + t2.z*xc.w + t2.w*xp.w + b4.w;
    o0 *= __fdividef(1.f, 1.f + __expf(-o0));
    o1 *= __fdividef(1.f, 1.f + __expf(-o1));
    o2 *= __fdividef(1.f, 1.f + __expf(-o2));
    o3 *= __fdividef(1.f, 1.f + __expf(-o3));
    *(float4*)(g_xb + (size_t)r*INNER + d4*4) = make_float4(o0, o1, o2, o3);
    union { __nv_bfloat162 h[2]; uint2 u; } pk;
    pk.h[0] = __floats2bfloat162_rn(o0, o1);
    pk.h[1] = __floats2bfloat162_rn(o2, o3);
    *(uint2*)(g_xbh + (size_t)r*INNER + d4*4) = pk.u;
}

// ---------------------------- selective scan + gating -----------------------
__global__ __launch_bounds__(128) void scan_kernel(
    const float* __restrict__ A_log, const float* __restrict__ Dp)
{
    __shared__ float s_dt[2][16][16];
    __shared__ float s_x [2][16][16];
    __shared__ float s_z [2][16][16];
    __shared__ float s_bc[2][16][32];
    __shared__ float s_y [16][16];

    int tid = threadIdx.x;
    int b  = blockIdx.x >> 7;
    int d0 = (blockIdx.x & 127) * 16;
    int q  = tid & 7, dl = tid >> 3;
    int d  = d0 + dl;

    float a0 = -__expf(A_log[d*STATE + 2*q]);
    float a1 = -__expf(A_log[d*STATE + 2*q + 1]);
    float Dd = Dp[d];
    size_t tokbase = (size_t)b * SEQ;

    uint32_t u_dt = (uint32_t)__cvta_generic_to_shared(&s_dt[0][0][0]);
    uint32_t u_x  = (uint32_t)__cvta_generic_to_shared(&s_x [0][0][0]);
    uint32_t u_z  = (uint32_t)__cvta_generic_to_shared(&s_z [0][0][0]);
    uint32_t u_bc = (uint32_t)__cvta_generic_to_shared(&s_bc[0][0][0]);

    auto stage = [&](int s) {
        int l0 = s * 16, buf = s & 1;
        #pragma unroll
        for (int ii = tid; ii < 320; ii += 128) {
            if (ii < 192) {
                int arr = ii >> 6, e = ii & 63;
                int rowi = e >> 2, c4 = e & 3;
                size_t tok = tokbase + l0 + rowi;
                uint32_t doff = (uint32_t)((rowi*16 + c4*4) * 4) + buf*1024;
                if (arr == 0)
                    cp16(u_dt + doff, g_dtbc + tok*NCAT + d0 + c4*4);
                else if (arr == 1)
                    cp16(u_x + doff, g_xb + tok*INNER + d0 + c4*4);
                else
                    cp16(u_z + doff, g_xz + tok*(2*INNER) + INNER + d0 + c4*4);
            } else {
                int e = ii - 192;
                int rowi = e >> 3, c8 = e & 7;
                size_t tok = tokbase + l0 + rowi;
                cp16(u_bc + buf*2048 + (uint32_t)((rowi*32 + c8*4) * 4),
                     g_dtbc + tok*NCAT + 2048 + c8*4);
            }
        }
    };

    stage(0); cp_commit();

    float h0 = 0.f, h1 = 0.f;
    for (int s = 0; s < SEQ/16; s++) {
        if (s + 1 < SEQ/16) { stage(s + 1); cp_commit(); cp_wait<1>(); }
        else cp_wait<0>();
        __syncthreads();

        int buf = s & 1;
        #pragma unroll
        for (int i = 0; i < 16; i++) {
            float dtc = s_dt[buf][i][dl];
            float xc  = s_x [buf][i][dl];
            float2 Bv = *(const float2*)&s_bc[buf][i][2*q];
            float2 Cv = *(const float2*)&s_bc[buf][i][16 + 2*q];
            float e0 = __expf(dtc * a0);
            float e1 = __expf(dtc * a1);
            float dx = dtc * xc;
            h0 = fmaf(e0, h0, dx * Bv.x);
            h1 = fmaf(e1, h1, dx * Bv.y);
            float p = fmaf(h1, Cv.y, h0 * Cv.x);
            p += __shfl_xor_sync(0xffffffffu, p, 1);
            p += __shfl_xor_sync(0xffffffffu, p, 2);
            p += __shfl_xor_sync(0xffffffffu, p, 4);
            if (q == 0) {
                float zz  = s_z[buf][i][dl];
                float sil = zz * __fdividef(1.f, 1.f + __expf(-zz));
                s_y[i][dl] = fmaf(Dd, xc, p) * sil;
            }
        }
        __syncthreads();
        if (tid < 64) {
            int rowi = tid >> 2, c4 = tid & 3;
            float4 v = *(float4*)&s_y[rowi][c4*4];
            *(float4*)(g_y + (tokbase + s*16 + rowi)*INNER + d0 + c4*4) = v;
        }
    }
}

// ------------------------------------------------------------------- launch
extern "C" void kernel_launch(void* const* d_in, const int* in_sizes, int n_in,
                              void* d_out, int out_size)
{
    const float* x    = (const float*)d_in[0];
    const float* ns   = (const float*)d_in[1];
    const float* nb   = (const float*)d_in[2];
    const float* Win  = (const float*)d_in[3];
    const float* cw   = (const float*)d_in[4];
    const float* cb   = (const float*)d_in[5];
    const float* Wdt  = (const float*)d_in[6];
    const float* bdt  = (const float*)d_in[7];
    const float* Alog = (const float*)d_in[8];
    const float* Dp   = (const float*)d_in[9];
    const float* WB   = (const float*)d_in[10];
    const float* WC   = (const float*)d_in[11];
    const float* Wout = (const float*)d_in[12];
    float* out = (float*)d_out;

    void *p_xnh, *p_xz, *p_xbh, *p_dtbc, *p_y, *p_winth, *p_wcatth, *p_woutt;
    cudaGetSymbolAddress(&p_xnh,  g_xnh);
    cudaGetSymbolAddress(&p_xz,   g_xz);
    cudaGetSymbolAddress(&p_xbh,  g_xbh);
    cudaGetSymbolAddress(&p_dtbc, g_dtbc);
    cudaGetSymbolAddress(&p_y,    g_y);
    cudaGetSymbolAddress(&p_winth,  g_WinTh);
    cudaGetSymbolAddress(&p_wcatth, g_WcatTh);
    cudaGetSymbolAddress(&p_woutt,  g_WoutT);
    __nv_bfloat16* xnh   = (__nv_bfloat16*)p_xnh;
    float*         xz    = (float*)p_xz;
    __nv_bfloat16* xbh   = (__nv_bfloat16*)p_xbh;
    float*         dtbc  = (float*)p_dtbc;
    float*         yv    = (float*)p_y;
    __nv_bfloat16* WinTh  = (__nv_bfloat16*)p_winth;
    __nv_bfloat16* WcatTh = (__nv_bfloat16*)p_wcatth;
    float*         WoutT  = (float*)p_woutt;

    cudaFuncSetAttribute(gemm_bf16k<0>, cudaFuncAttributeMaxDynamicSharedMemorySize, GSMEMH);
    cudaFuncSetAttribute(gemm_bf16k<1>, cudaFuncAttributeMaxDynamicSharedMemorySize, GSMEMH);
    cudaFuncSetAttribute(gemm_tf32k,    cudaFuncAttributeMaxDynamicSharedMemorySize, GSMEM_T);

    // launch order arranged so gemm_bf16k<0> is the 4th launch (ncu target)
    // 1) Win -> WinTh (bf16)
    tr_bf16<<<dim3(2*INNER/32, HIDDEN/32), dim3(32,8)>>>(Win, WinTh, HIDDEN, 2*INNER);
    // 2) LayerNorm -> bf16
    ln_kernel<<<TOK, 256>>>(x, ns, nb);
    // 3) WB/WC rows of WcatTh
    wbc_kernel<<<(256*2048)/256, 256>>>(WB, WC);
    // 4) xz = xn @ W_in   (bf16 mma)  <-- profiled
    gemm_bf16k<0><<<dim3(2*INNER/256, TOK/128), 256, GSMEMH>>>(
        xnh, WinTh, xz, TOK, 2*INNER, HIDDEN, nullptr);
    // 5) Wdt -> WcatTh rows 0..2047
    tr_bf16<<<dim3(INNER/32, INNER/32), dim3(32,8)>>>(Wdt, WcatTh, INNER, INNER);
    // 6) conv + SiLU (fp32 + bf16 outputs)
    conv_kernel<<<(TOK*INNER/4)/256, 256>>>(cw, cb);
    // 7) [dt | B | C] = xb @ Wcat  (bf16 mma, softplus on dt cols)
    gemm_bf16k<1><<<dim3(NCAT/256, TOK/128), 256, GSMEMH>>>(
        xbh, WcatTh, dtbc, TOK, NCAT, INNER, bdt);
    // 8) Wout -> WoutT (tf32)
    tr_tf32<<<dim3(HIDDEN/32, INNER/32), dim3(32,8)>>>(Wout, WoutT, INNER, HIDDEN);
    // 9) selective scan + gating
    scan_kernel<<<512, 128>>>(Alog, Dp);
    // 10) out = x + y @ W_out  (tf32 mma)
    gemm_tf32k<<<dim3(HIDDEN/256, TOK/128), 256, GSMEM_T>>>(
        yv, WoutT, out, TOK, HIDDEN, INNER, x);
}

// round 12
// speedup vs baseline: 4.8083x; 1.1469x over previous
#include <cuda_runtime.h>
#include <cuda_bf16.h>
#include <cstdint>
#include <math.h>

#define HIDDEN 1024
#define INNER  2048
#define STATE  16
#define BATCH  4
#define SEQ    2048
#define TOK    (BATCH*SEQ)   // 8192
#define NCAT   2304          // 2048 dt | 16 B | 16 C | 224 pad (9 tiles of 256)

// ---------------- scratch (static device globals) ---------------------------
__device__ __nv_bfloat16 g_xnh[TOK*HIDDEN];      // ln output (bf16, GEMM1 A)
__device__ float g_xz[TOK*2*INNER];              // GEMM1 out [xb_raw | z] fp32
__device__ float g_xb[TOK*INNER];                // conv+silu fp32 (scan)
__device__ __nv_bfloat16 g_xbh[TOK*INNER];       // conv+silu bf16 (GEMM2 A)
__device__ float g_dtbc[TOK*NCAT];               // [softplus(dt) | B | C | pad]
__device__ __nv_bfloat16 g_yh[TOK*INNER];        // gated SSM output (bf16, GEMM3 A)
__device__ __nv_bfloat16 g_WinTh [2*INNER*HIDDEN];
__device__ __nv_bfloat16 g_WcatTh[NCAT*INNER];
__device__ __nv_bfloat16 g_WoutTh[HIDDEN*INNER];

// ============================== helpers =====================================
__device__ __forceinline__ void cp16(uint32_t s, const void* g) {
    asm volatile("cp.async.cg.shared.global [%0], [%1], 16;" :: "r"(s), "l"(g));
}
__device__ __forceinline__ void cp_commit() {
    asm volatile("cp.async.commit_group;" ::: "memory");
}
template<int N> __device__ __forceinline__ void cp_wait() {
    asm volatile("cp.async.wait_group %0;" :: "n"(N) : "memory");
}
__device__ __forceinline__ void mma_bf16(float* d, const uint32_t* a, const uint32_t* b) {
    asm volatile("mma.sync.aligned.m16n8k16.row.col.f32.bf16.bf16.f32 "
                 "{%0,%1,%2,%3},{%4,%5,%6,%7},{%8,%9},{%0,%1,%2,%3};"
                 : "+f"(d[0]), "+f"(d[1]), "+f"(d[2]), "+f"(d[3])
                 : "r"(a[0]), "r"(a[1]), "r"(a[2]), "r"(a[3]), "r"(b[0]), "r"(b[1]));
}
__device__ __forceinline__ void ldmx4(uint32_t* r, uint32_t addr) {
    asm volatile("ldmatrix.sync.aligned.m8n8.x4.shared.b16 {%0,%1,%2,%3}, [%4];"
                 : "=r"(r[0]), "=r"(r[1]), "=r"(r[2]), "=r"(r[3]) : "r"(addr));
}
__device__ __forceinline__ float softplus_f(float v) {
    return fmaxf(v, 0.f) + __logf(1.f + __expf(-fabsf(v)));
}

// ====================== bf16 mma.sync GEMM (ldmatrix) =======================
// C[M,N] = A[M,K] @ Bt[N,K]^T, bf16 in, fp32 acc/out.
// BM=128, BN=256, BK=32, 256 threads (2x4 warps, 64x64 warp tiles),
// 4-stage cp.async pipeline. Rows padded to 80 B -> LDSM conflict-free.
// EPI: 0 plain, 1 mixed softplus(dt)|raw(bc), 2 +residual
#define PADH_B 80
#define AH_STAGE_B (128*PADH_B)               // 10240
#define BH_STAGE_B (256*PADH_B)               // 20480
#define GSMEMH (4*(AH_STAGE_B + BH_STAGE_B))  // 122880

template<int EPI>
__global__ __launch_bounds__(256) void gemm_bf16k(
    const __nv_bfloat16* __restrict__ A, const __nv_bfloat16* __restrict__ Bt,
    float* __restrict__ C, int M, int N, int K,
    const float* __restrict__ bias, const float* __restrict__ resid)
{
    extern __shared__ char smemc[];
    char* Abase = smemc;
    char* Bbase = smemc + 4*AH_STAGE_B;

    int tid = threadIdx.x, lane = tid & 31, wid = tid >> 5;
    int wm = wid >> 2, wn = wid & 3;
    int m0 = blockIdx.y * 128, n0 = blockIdx.x * 256;

    uint32_t uA = (uint32_t)__cvta_generic_to_shared(Abase);
    uint32_t uB = (uint32_t)__cvta_generic_to_shared(Bbase);

    const __nv_bfloat16* Agm = A  + (size_t)m0 * K;
    const __nv_bfloat16* Bgm = Bt + (size_t)n0 * K;

    int ns = K >> 5;                          // BK = 32

    auto load_stage = [&](int s) {
        int buf = s & 3;
        const __nv_bfloat16* Ak = Agm + s * 32;
        const __nv_bfloat16* Bk = Bgm + s * 32;
        uint32_t ab = uA + buf * AH_STAGE_B;
        uint32_t bb = uB + buf * BH_STAGE_B;
        #pragma unroll
        for (int i = 0; i < 2; i++) {         // A: 128 rows x 64 B
            int e = tid + i * 256;
            int row = e >> 2, c4 = e & 3;
            cp16(ab + (uint32_t)(row*PADH_B + c4*16), Ak + (size_t)row * K + c4*8);
        }
        #pragma unroll
        for (int i = 0; i < 4; i++) {         // B: 256 rows x 64 B
            int e = tid + i * 256;
            int row = e >> 2, c4 = e & 3;
            cp16(bb + (uint32_t)(row*PADH_B + c4*16), Bk + (size_t)row * K + c4*8);
        }
        cp_commit();
    };

    load_stage(0); load_stage(1); load_stage(2);

    float acc[4][8][4] = {};

    // ldmatrix lane-offset maps (bytes):
    // A groups: g0 rows0-7 +0 | g1 rows8-15 +0 | g2 rows0-7 +16 | g3 rows8-15 +16
    uint32_t aOff = (uint32_t)(((lane & 7) + ((lane >> 3) & 1) * 8) * PADH_B
                               + (lane >> 4) * 16);
    // B groups: g0 n0-7 +0 | g1 n0-7 +16 | g2 n8-15 +0 | g3 n8-15 +16
    uint32_t bOff = (uint32_t)(((lane & 7) + (lane >> 4) * 8) * PADH_B
                               + ((lane >> 3) & 1) * 16);
    uint32_t aWarp = uA + (uint32_t)(wm*64*PADH_B) + aOff;
    uint32_t bWarp = uB + (uint32_t)(wn*64*PADH_B) + bOff;

    for (int s = 0; s < ns; s++) {
        cp_wait<2>();
        __syncthreads();
        if (s + 3 < ns) load_stage(s + 3);

        int buf = s & 3;
        uint32_t aStage = aWarp + buf * AH_STAGE_B;
        uint32_t bStage = bWarp + buf * BH_STAGE_B;
        #pragma unroll
        for (int ks = 0; ks < 2; ks++) {      // two k16 slices
            uint32_t af[4][4], bf[4][4];
            #pragma unroll
            for (int am = 0; am < 4; am++)
                ldmx4(af[am], aStage + (uint32_t)(am*16*PADH_B + ks*32));
            #pragma unroll
            for (int bp = 0; bp < 4; bp++)
                ldmx4(bf[bp], bStage + (uint32_t)(bp*16*PADH_B + ks*32));
            #pragma unroll
            for (int am = 0; am < 4; am++)
                #pragma unroll
                for (int bn = 0; bn < 8; bn++)
                    mma_bf16(acc[am][bn], af[am], &bf[bn >> 1][(bn & 1) * 2]);
        }
    }

    int r = lane >> 2, c = lane & 3;
    #pragma unroll
    for (int am = 0; am < 4; am++) {
        int row0 = m0 + wm*64 + am*16 + r;
        #pragma unroll
        for (int bn = 0; bn < 8; bn++) {
            int col = n0 + wn*64 + bn*8 + 2*c;
            #pragma unroll
            for (int h = 0; h < 2; h++) {
                int row = row0 + h*8;
                float v0 = acc[am][bn][h*2 + 0];
                float v1 = acc[am][bn][h*2 + 1];
                if (EPI == 1) {
                    if (col < 2048) {
                        v0 = softplus_f(v0 + bias[col]);
                        v1 = softplus_f(v1 + bias[col + 1]);
                    }
                } else if (EPI == 2) {
                    const float* rp = resid + (size_t)row * N + col;
                    v0 += rp[0]; v1 += rp[1];
                }
                *(float2*)(C + (size_t)row * N + col) = make_float2(v0, v1);
            }
        }
    }
}

// ------------------------------- weight prep --------------------------------
__global__ __launch_bounds__(256) void tr_bf16(
    const float* __restrict__ in, __nv_bfloat16* __restrict__ out, int K, int N)
{   // in [K,N] fp32 -> out [N,K] bf16
    __shared__ float tile[32][33];
    int tx = threadIdx.x, ty = threadIdx.y;
    int x = blockIdx.x * 32 + tx;
    int y = blockIdx.y * 32 + ty;
    #pragma unroll
    for (int j = 0; j < 32; j += 8)
        tile[ty + j][tx] = in[(size_t)(y + j) * N + x];
    __syncthreads();
    int x2 = blockIdx.y * 32 + tx;
    int y2 = blockIdx.x * 32 + ty;
    #pragma unroll
    for (int j = 0; j < 32; j += 8)
        out[(size_t)(y2 + j) * K + x2] = __float2bfloat16(tile[tx][ty + j]);
}

__global__ __launch_bounds__(256) void wbc_kernel(
    const float* __restrict__ WB, const float* __restrict__ WC)
{   // rows 2048..2303 of g_WcatTh: W_B^T, W_C^T, zeros
    int idx = blockIdx.x * 256 + threadIdx.x;     // 256*2048
    int j = idx >> 11, k = idx & 2047;
    float v = (j < 16) ? WB[(size_t)k*STATE + j]
            : (j < 32) ? WC[(size_t)k*STATE + (j - 16)]
            : 0.f;
    g_WcatTh[(size_t)(2048 + j) * INNER + k] = __float2bfloat16(v);
}

// ---------------------------------------------------------------- LayerNorm
__global__ __launch_bounds__(256) void ln_kernel(
    const float* __restrict__ x, const float* __restrict__ g,
    const float* __restrict__ bt)
{
    int r = blockIdx.x, t = threadIdx.x;
    float4 v = *(const float4*)(x + (size_t)r*HIDDEN + t*4);
    float s  = v.x + v.y + v.z + v.w;
    float s2 = v.x*v.x + v.y*v.y + v.z*v.z + v.w*v.w;
    #pragma unroll
    for (int off = 16; off > 0; off >>= 1) {
        s  += __shfl_xor_sync(0xffffffffu, s,  off);
        s2 += __shfl_xor_sync(0xffffffffu, s2, off);
    }
    __shared__ float a1[8], a2[8];
    if ((t & 31) == 0) { a1[t >> 5] = s; a2[t >> 5] = s2; }
    __syncthreads();
    float ts = 0.f, ts2 = 0.f;
    #pragma unroll
    for (int i = 0; i < 8; i++) { ts += a1[i]; ts2 += a2[i]; }
    float mu   = ts * (1.f / HIDDEN);
    float var  = fmaf(ts2, 1.f / HIDDEN, -mu * mu);
    float rstd = rsqrtf(var + 1e-5f);
    float4 g4 = *(const float4*)(g  + t*4);
    float4 b4 = *(const float4*)(bt + t*4);
    float4 ov;
    ov.x = (v.x - mu) * rstd * g4.x + b4.x;
    ov.y = (v.y - mu) * rstd * g4.y + b4.y;
    ov.z = (v.z - mu) * rstd * g4.z + b4.z;
    ov.w = (v.w - mu) * rstd * g4.w + b4.w;
    union { __nv_bfloat162 h[2]; uint2 u; } pk;
    pk.h[0] = __floats2bfloat162_rn(ov.x, ov.y);
    pk.h[1] = __floats2bfloat162_rn(ov.z, ov.w);
    *(uint2*)(g_xnh + (size_t)r*HIDDEN + t*4) = pk.u;
}

// ----------------------------------------------- depthwise conv (k=3) + SiLU
__global__ __launch_bounds__(256) void conv_kernel(
    const float* __restrict__ cw, const float* __restrict__ cb)
{
    int idx = blockIdx.x * 256 + threadIdx.x;
    int d4 = idx & 511;
    int r  = idx >> 9;
    int l  = r & (SEQ - 1);
    const float* base = g_xz + (size_t)r*(2*INNER) + d4*4;
    float4 zero = make_float4(0.f, 0.f, 0.f, 0.f);
    float4 xm = (l > 0)       ? *(const float4*)(base - 2*INNER) : zero;
    float4 xc = *(const float4*)(base);
    float4 xp = (l < SEQ - 1) ? *(const float4*)(base + 2*INNER) : zero;
    const float4* cwp = (const float4*)(cw + d4*12);
    float4 t0 = cwp[0], t1 = cwp[1], t2 = cwp[2];
    float4 b4 = *(const float4*)(cb + d4*4);
    float o0 = t0.x*xm.x + t0.y*xc.x + t0.z*xp.x + b4.x;
    float o1 = t0.w*xm.y + t1.x*xc.y + t1.y*xp.y + b4.y;
    float o2 = t1.z*xm.z + t1.w*xc.z + t2.x*xp.z + b4.z;
    float o3 = t2.y*xm.w + t2.z*xc.w + t2.w*xp.w + b4.w;
    o0 *= __fdividef(1.f, 1.f + __expf(-o0));
    o1 *= __fdividef(1.f, 1.f + __expf(-o1));
    o2 *= __fdividef(1.f, 1.f + __expf(-o2));
    o3 *= __fdividef(1.f, 1.f + __expf(-o3));
    *(float4*)(g_xb + (size_t)r*INNER + d4*4) = make_float4(o0, o1, o2, o3);
    union { __nv_bfloat162 h[2]; uint2 u; } pk;
    pk.h[0] = __floats2bfloat162_rn(o0, o1);
    pk.h[1] = __floats2bfloat162_rn(o2, o3);
    *(uint2*)(g_xbh + (size_t)r*INNER + d4*4) = pk.u;
}

// ---------------------------- selective scan + gating -----------------------
__global__ __launch_bounds__(128) void scan_kernel(
    const float* __restrict__ A_log, const float* __restrict__ Dp)
{
    __shared__ float s_dt[2][16][16];
    __shared__ float s_x [2][16][16];
    __shared__ float s_z [2][16][16];
    __shared__ float s_bc[2][16][32];
    __shared__ float s_y [16][16];

    int tid = threadIdx.x;
    int b  = blockIdx.x >> 7;
    int d0 = (blockIdx.x & 127) * 16;
    int q  = tid & 7, dl = tid >> 3;
    int d  = d0 + dl;

    float a0 = -__expf(A_log[d*STATE + 2*q]);
    float a1 = -__expf(A_log[d*STATE + 2*q + 1]);
    float Dd = Dp[d];
    size_t tokbase = (size_t)b * SEQ;

    uint32_t u_dt = (uint32_t)__cvta_generic_to_shared(&s_dt[0][0][0]);
    uint32_t u_x  = (uint32_t)__cvta_generic_to_shared(&s_x [0][0][0]);
    uint32_t u_z  = (uint32_t)__cvta_generic_to_shared(&s_z [0][0][0]);
    uint32_t u_bc = (uint32_t)__cvta_generic_to_shared(&s_bc[0][0][0]);

    auto stage = [&](int s) {
        int l0 = s * 16, buf = s & 1;
        #pragma unroll
        for (int ii = tid; ii < 320; ii += 128) {
            if (ii < 192) {
                int arr = ii >> 6, e = ii & 63;
                int rowi = e >> 2, c4 = e & 3;
                size_t tok = tokbase + l0 + rowi;
                uint32_t doff = (uint32_t)((rowi*16 + c4*4) * 4) + buf*1024;
                if (arr == 0)
                    cp16(u_dt + doff, g_dtbc + tok*NCAT + d0 + c4*4);
                else if (arr == 1)
                    cp16(u_x + doff, g_xb + tok*INNER + d0 + c4*4);
                else
                    cp16(u_z + doff, g_xz + tok*(2*INNER) + INNER + d0 + c4*4);
            } else {
                int e = ii - 192;
                int rowi = e >> 3, c8 = e & 7;
                size_t tok = tokbase + l0 + rowi;
                cp16(u_bc + buf*2048 + (uint32_t)((rowi*32 + c8*4) * 4),
                     g_dtbc + tok*NCAT + 2048 + c8*4);
            }
        }
    };

    stage(0); cp_commit();

    float h0 = 0.f, h1 = 0.f;
    for (int s = 0; s < SEQ/16; s++) {
        if (s + 1 < SEQ/16) { stage(s + 1); cp_commit(); cp_wait<1>(); }
        else cp_wait<0>();
        __syncthreads();

        int buf = s & 1;
        #pragma unroll
        for (int i = 0; i < 16; i++) {
            float dtc = s_dt[buf][i][dl];
            float xc  = s_x [buf][i][dl];
            float2 Bv = *(const float2*)&s_bc[buf][i][2*q];
            float2 Cv = *(const float2*)&s_bc[buf][i][16 + 2*q];
            float e0 = __expf(dtc * a0);
            float e1 = __expf(dtc * a1);
            float dx = dtc * xc;
            h0 = fmaf(e0, h0, dx * Bv.x);
            h1 = fmaf(e1, h1, dx * Bv.y);
            float p = fmaf(h1, Cv.y, h0 * Cv.x);
            p += __shfl_xor_sync(0xffffffffu, p, 1);
            p += __shfl_xor_sync(0xffffffffu, p, 2);
            p += __shfl_xor_sync(0xffffffffu, p, 4);
            if (q == 0) {
                float zz  = s_z[buf][i][dl];
                float sil = zz * __fdividef(1.f, 1.f + __expf(-zz));
                s_y[i][dl] = fmaf(Dd, xc, p) * sil;
            }
        }
        __syncthreads();
        if (tid < 64) {
            int rowi = tid >> 2, c4 = tid & 3;
            float4 v = *(float4*)&s_y[rowi][c4*4];
            union { __nv_bfloat162 h[2]; uint2 u; } pk;
            pk.h[0] = __floats2bfloat162_rn(v.x, v.y);
            pk.h[1] = __floats2bfloat162_rn(v.z, v.w);
            *(uint2*)(g_yh + (tokbase + s*16 + rowi)*INNER + d0 + c4*4) = pk.u;
        }
    }
}

// ------------------------------------------------------------------- launch
extern "C" void kernel_launch(void* const* d_in, const int* in_sizes, int n_in,
                              void* d_out, int out_size)
{
    const float* x    = (const float*)d_in[0];
    const float* ns   = (const float*)d_in[1];
    const float* nb   = (const float*)d_in[2];
    const float* Win  = (const float*)d_in[3];
    const float* cw   = (const float*)d_in[4];
    const float* cb   = (const float*)d_in[5];
    const float* Wdt  = (const float*)d_in[6];
    const float* bdt  = (const float*)d_in[7];
    const float* Alog = (const float*)d_in[8];
    const float* Dp   = (const float*)d_in[9];
    const float* WB   = (const float*)d_in[10];
    const float* WC   = (const float*)d_in[11];
    const float* Wout = (const float*)d_in[12];
    float* out = (float*)d_out;

    void *p_xnh, *p_xz, *p_xbh, *p_dtbc, *p_yh, *p_winth, *p_wcatth, *p_woutth;
    cudaGetSymbolAddress(&p_xnh,  g_xnh);
    cudaGetSymbolAddress(&p_xz,   g_xz);
    cudaGetSymbolAddress(&p_xbh,  g_xbh);
    cudaGetSymbolAddress(&p_dtbc, g_dtbc);
    cudaGetSymbolAddress(&p_yh,   g_yh);
    cudaGetSymbolAddress(&p_winth,  g_WinTh);
    cudaGetSymbolAddress(&p_wcatth, g_WcatTh);
    cudaGetSymbolAddress(&p_woutth, g_WoutTh);
    __nv_bfloat16* xnh   = (__nv_bfloat16*)p_xnh;
    float*         xz    = (float*)p_xz;
    __nv_bfloat16* xbh   = (__nv_bfloat16*)p_xbh;
    float*         dtbc  = (float*)p_dtbc;
    __nv_bfloat16* yh    = (__nv_bfloat16*)p_yh;
    __nv_bfloat16* WinTh  = (__nv_bfloat16*)p_winth;
    __nv_bfloat16* WcatTh = (__nv_bfloat16*)p_wcatth;
    __nv_bfloat16* WoutTh = (__nv_bfloat16*)p_woutth;

    cudaFuncSetAttribute(gemm_bf16k<0>, cudaFuncAttributeMaxDynamicSharedMemorySize, GSMEMH);
    cudaFuncSetAttribute(gemm_bf16k<1>, cudaFuncAttributeMaxDynamicSharedMemorySize, GSMEMH);
    cudaFuncSetAttribute(gemm_bf16k<2>, cudaFuncAttributeMaxDynamicSharedMemorySize, GSMEMH);

    // launch order: gemm_bf16k<0> is the 4th launch (ncu target)
    // 1) Win -> WinTh (bf16)
    tr_bf16<<<dim3(2*INNER/32, HIDDEN/32), dim3(32,8)>>>(Win, WinTh, HIDDEN, 2*INNER);
    // 2) LayerNorm -> bf16
    ln_kernel<<<TOK, 256>>>(x, ns, nb);
    // 3) WB/WC rows of WcatTh
    wbc_kernel<<<(256*2048)/256, 256>>>(WB, WC);
    // 4) xz = xn @ W_in   (bf16 mma)  <-- profiled
    gemm_bf16k<0><<<dim3(2*INNER/256, TOK/128), 256, GSMEMH>>>(
        xnh, WinTh, xz, TOK, 2*INNER, HIDDEN, nullptr, nullptr);
    // 5) Wdt -> WcatTh rows 0..2047
    tr_bf16<<<dim3(INNER/32, INNER/32), dim3(32,8)>>>(Wdt, WcatTh, INNER, INNER);
    // 6) conv + SiLU (fp32 + bf16 outputs)
    conv_kernel<<<(TOK*INNER/4)/256, 256>>>(cw, cb);
    // 7) [dt | B | C] = xb @ Wcat  (bf16 mma, softplus on dt cols)
    gemm_bf16k<1><<<dim3(NCAT/256, TOK/128), 256, GSMEMH>>>(
        xbh, WcatTh, dtbc, TOK, NCAT, INNER, bdt, nullptr);
    // 8) Wout -> WoutTh (bf16)
    tr_bf16<<<dim3(HIDDEN/32, INNER/32), dim3(32,8)>>>(Wout, WoutTh, INNER, HIDDEN);
    // 9) selective scan + gating -> bf16 y
    scan_kernel<<<512, 128>>>(Alog, Dp);
    // 10) out = x + y @ W_out  (bf16 mma + fp32 residual)
    gemm_bf16k<2><<<dim3(HIDDEN/256, TOK/128), 256, GSMEMH>>>(
        yh, WoutTh, out, TOK, HIDDEN, INNER, nullptr, x);
}

// round 13
// speedup vs baseline: 4.8294x; 1.0044x over previous
#include <cuda_runtime.h>
#include <cuda_bf16.h>
#include <cstdint>
#include <math.h>

#define HIDDEN 1024
#define INNER  2048
#define STATE  16
#define BATCH  4
#define SEQ    2048
#define TOK    (BATCH*SEQ)   // 8192
#define NCAT   2304          // 2048 dt | 16 B | 16 C | 224 pad (9 tiles of 256)

// ---------------- scratch (static device globals) ---------------------------
__device__ __nv_bfloat16 g_xnh[TOK*HIDDEN];      // ln output (bf16, GEMM1 A)
__device__ float g_xz[TOK*2*INNER];              // GEMM1 out [xb_raw | z] fp32
__device__ float g_xb[TOK*INNER];                // conv+silu fp32 (scan)
__device__ __nv_bfloat16 g_xbh[TOK*INNER];       // conv+silu bf16 (GEMM2 A)
__device__ float g_dtbc[TOK*NCAT];               // [softplus(dt) | B | C | pad]
__device__ __nv_bfloat16 g_yh[TOK*INNER];        // gated SSM output (bf16, GEMM3 A)
__device__ __nv_bfloat16 g_WinTh [2*INNER*HIDDEN];
__device__ __nv_bfloat16 g_WcatTh[NCAT*INNER];
__device__ __nv_bfloat16 g_WoutTh[HIDDEN*INNER];

// ============================== helpers =====================================
__device__ __forceinline__ void cp16(uint32_t s, const void* g) {
    asm volatile("cp.async.cg.shared.global [%0], [%1], 16;" :: "r"(s), "l"(g));
}
__device__ __forceinline__ void cp_commit() {
    asm volatile("cp.async.commit_group;" ::: "memory");
}
template<int N> __device__ __forceinline__ void cp_wait() {
    asm volatile("cp.async.wait_group %0;" :: "n"(N) : "memory");
}
__device__ __forceinline__ void mma_bf16(float* d, const uint32_t* a, const uint32_t* b) {
    asm volatile("mma.sync.aligned.m16n8k16.row.col.f32.bf16.bf16.f32 "
                 "{%0,%1,%2,%3},{%4,%5,%6,%7},{%8,%9},{%0,%1,%2,%3};"
                 : "+f"(d[0]), "+f"(d[1]), "+f"(d[2]), "+f"(d[3])
                 : "r"(a[0]), "r"(a[1]), "r"(a[2]), "r"(a[3]), "r"(b[0]), "r"(b[1]));
}
__device__ __forceinline__ void ldmx4(uint32_t* r, uint32_t addr) {
    asm volatile("ldmatrix.sync.aligned.m8n8.x4.shared.b16 {%0,%1,%2,%3}, [%4];"
                 : "=r"(r[0]), "=r"(r[1]), "=r"(r[2]), "=r"(r[3]) : "r"(addr));
}
__device__ __forceinline__ float softplus_f(float v) {
    return fmaxf(v, 0.f) + __logf(1.f + __expf(-fabsf(v)));
}

// ====================== bf16 mma.sync GEMM (ldmatrix, frag-pipelined) =======
// C[M,N] = A[M,K] @ Bt[N,K]^T, bf16 in, fp32 acc/out.
// BM=128, BN=256, BK=32, 256 threads (2x4 warps, 64x64 warp tiles),
// 4-stage cp.async pipeline + double-buffered LDSM fragments.
// EPI: 0 plain, 1 mixed softplus(dt)|raw(bc), 2 +residual
#define PADH_B 80
#define AH_STAGE_B (128*PADH_B)               // 10240
#define BH_STAGE_B (256*PADH_B)               // 20480
#define GSMEMH (4*(AH_STAGE_B + BH_STAGE_B))  // 122880

template<int EPI>
__global__ __launch_bounds__(256) void gemm_bf16k(
    const __nv_bfloat16* __restrict__ A, const __nv_bfloat16* __restrict__ Bt,
    float* __restrict__ C, int M, int N, int K,
    const float* __restrict__ bias, const float* __restrict__ resid)
{
    extern __shared__ char smemc[];
    char* Abase = smemc;
    char* Bbase = smemc + 4*AH_STAGE_B;

    int tid = threadIdx.x, lane = tid & 31, wid = tid >> 5;
    int wm = wid >> 2, wn = wid & 3;
    int m0 = blockIdx.y * 128, n0 = blockIdx.x * 256;

    uint32_t uA = (uint32_t)__cvta_generic_to_shared(Abase);
    uint32_t uB = (uint32_t)__cvta_generic_to_shared(Bbase);

    const __nv_bfloat16* Agm = A  + (size_t)m0 * K;
    const __nv_bfloat16* Bgm = Bt + (size_t)n0 * K;

    int ns = K >> 5;                          // BK = 32

    auto load_stage = [&](int s) {
        int buf = s & 3;
        const __nv_bfloat16* Ak = Agm + s * 32;
        const __nv_bfloat16* Bk = Bgm + s * 32;
        uint32_t ab = uA + buf * AH_STAGE_B;
        uint32_t bb = uB + buf * BH_STAGE_B;
        #pragma unroll
        for (int i = 0; i < 2; i++) {
            int e = tid + i * 256;
            int row = e >> 2, c4 = e & 3;
            cp16(ab + (uint32_t)(row*PADH_B + c4*16), Ak + (size_t)row * K + c4*8);
        }
        #pragma unroll
        for (int i = 0; i < 4; i++) {
            int e = tid + i * 256;
            int row = e >> 2, c4 = e & 3;
            cp16(bb + (uint32_t)(row*PADH_B + c4*16), Bk + (size_t)row * K + c4*8);
        }
        cp_commit();
    };

    load_stage(0); load_stage(1); load_stage(2);

    float acc[4][8][4] = {};
    uint32_t af[2][4][4], bf[2][4][4];

    // ldmatrix lane-offset maps (bytes)
    uint32_t aOff = (uint32_t)(((lane & 7) + ((lane >> 3) & 1) * 8) * PADH_B
                               + (lane >> 4) * 16);
    uint32_t bOff = (uint32_t)(((lane & 7) + (lane >> 4) * 8) * PADH_B
                               + ((lane >> 3) & 1) * 16);
    uint32_t aWarp = uA + (uint32_t)(wm*64*PADH_B) + aOff;
    uint32_t bWarp = uB + (uint32_t)(wn*64*PADH_B) + bOff;

    auto ldsm_slice = [&](uint32_t* afp, uint32_t* bfp, int buf, int ks) {
        uint32_t aStage = aWarp + buf * AH_STAGE_B + ks * 32;
        uint32_t bStage = bWarp + buf * BH_STAGE_B + ks * 32;
        #pragma unroll
        for (int am = 0; am < 4; am++)
            ldmx4(afp + am*4, aStage + (uint32_t)(am*16*PADH_B));
        #pragma unroll
        for (int bp = 0; bp < 4; bp++)
            ldmx4(bfp + bp*4, bStage + (uint32_t)(bp*16*PADH_B));
    };
    auto mma_all = [&](const uint32_t* afp, const uint32_t* bfp) {
        #pragma unroll
        for (int am = 0; am < 4; am++)
            #pragma unroll
            for (int bn = 0; bn < 8; bn++)
                mma_bf16(acc[am][bn], afp + am*4, bfp + (bn >> 1)*4 + (bn & 1)*2);
    };

    cp_wait<2>(); __syncthreads();
    ldsm_slice(&af[0][0][0], &bf[0][0][0], 0, 0);

    for (int s = 0; s < ns; s++) {
        // prefetch slice (s, ks=1), smem for stage s is ready
        ldsm_slice(&af[1][0][0], &bf[1][0][0], s & 3, 1);
        mma_all(&af[0][0][0], &bf[0][0][0]);
        if (s + 1 < ns) {
            cp_wait<1>(); __syncthreads();
            if (s + 3 < ns) load_stage(s + 3);
            // prefetch slice (s+1, ks=0) while mma of (s, ks=1) runs
            ldsm_slice(&af[0][0][0], &bf[0][0][0], (s + 1) & 3, 0);
        }
        mma_all(&af[1][0][0], &bf[1][0][0]);
    }

    int r = lane >> 2, c = lane & 3;
    #pragma unroll
    for (int am = 0; am < 4; am++) {
        int row0 = m0 + wm*64 + am*16 + r;
        #pragma unroll
        for (int bn = 0; bn < 8; bn++) {
            int col = n0 + wn*64 + bn*8 + 2*c;
            #pragma unroll
            for (int h = 0; h < 2; h++) {
                int row = row0 + h*8;
                float v0 = acc[am][bn][h*2 + 0];
                float v1 = acc[am][bn][h*2 + 1];
                if (EPI == 1) {
                    if (col < 2048) {
                        v0 = softplus_f(v0 + bias[col]);
                        v1 = softplus_f(v1 + bias[col + 1]);
                    }
                } else if (EPI == 2) {
                    const float* rp = resid + (size_t)row * N + col;
                    v0 += rp[0]; v1 += rp[1];
                }
                *(float2*)(C + (size_t)row * N + col) = make_float2(v0, v1);
            }
        }
    }
}

// ------------------------------- weight prep --------------------------------
__global__ __launch_bounds__(256) void tr_bf16(
    const float* __restrict__ in, __nv_bfloat16* __restrict__ out, int K, int N)
{   // in [K,N] fp32 -> out [N,K] bf16
    __shared__ float tile[32][33];
    int tx = threadIdx.x, ty = threadIdx.y;
    int x = blockIdx.x * 32 + tx;
    int y = blockIdx.y * 32 + ty;
    #pragma unroll
    for (int j = 0; j < 32; j += 8)
        tile[ty + j][tx] = in[(size_t)(y + j) * N + x];
    __syncthreads();
    int x2 = blockIdx.y * 32 + tx;
    int y2 = blockIdx.x * 32 + ty;
    #pragma unroll
    for (int j = 0; j < 32; j += 8)
        out[(size_t)(y2 + j) * K + x2] = __float2bfloat16(tile[tx][ty + j]);
}

__global__ __launch_bounds__(256) void wbc_kernel(
    const float* __restrict__ WB, const float* __restrict__ WC)
{   // rows 2048..2303 of g_WcatTh: W_B^T, W_C^T, zeros
    int idx = blockIdx.x * 256 + threadIdx.x;     // 256*2048
    int j = idx >> 11, k = idx & 2047;
    float v = (j < 16) ? WB[(size_t)k*STATE + j]
            : (j < 32) ? WC[(size_t)k*STATE + (j - 16)]
            : 0.f;
    g_WcatTh[(size_t)(2048 + j) * INNER + k] = __float2bfloat16(v);
}

// ---------------------------------------------------------------- LayerNorm
__global__ __launch_bounds__(256) void ln_kernel(
    const float* __restrict__ x, const float* __restrict__ g,
    const float* __restrict__ bt)
{
    int r = blockIdx.x, t = threadIdx.x;
    float4 v = *(const float4*)(x + (size_t)r*HIDDEN + t*4);
    float s  = v.x + v.y + v.z + v.w;
    float s2 = v.x*v.x + v.y*v.y + v.z*v.z + v.w*v.w;
    #pragma unroll
    for (int off = 16; off > 0; off >>= 1) {
        s  += __shfl_xor_sync(0xffffffffu, s,  off);
        s2 += __shfl_xor_sync(0xffffffffu, s2, off);
    }
    __shared__ float a1[8], a2[8];
    if ((t & 31) == 0) { a1[t >> 5] = s; a2[t >> 5] = s2; }
    __syncthreads();
    float ts = 0.f, ts2 = 0.f;
    #pragma unroll
    for (int i = 0; i < 8; i++) { ts += a1[i]; ts2 += a2[i]; }
    float mu   = ts * (1.f / HIDDEN);
    float var  = fmaf(ts2, 1.f / HIDDEN, -mu * mu);
    float rstd = rsqrtf(var + 1e-5f);
    float4 g4 = *(const float4*)(g  + t*4);
    float4 b4 = *(const float4*)(bt + t*4);
    float4 ov;
    ov.x = (v.x - mu) * rstd * g4.x + b4.x;
    ov.y = (v.y - mu) * rstd * g4.y + b4.y;
    ov.z = (v.z - mu) * rstd * g4.z + b4.z;
    ov.w = (v.w - mu) * rstd * g4.w + b4.w;
    union { __nv_bfloat162 h[2]; uint2 u; } pk;
    pk.h[0] = __floats2bfloat162_rn(ov.x, ov.y);
    pk.h[1] = __floats2bfloat162_rn(ov.z, ov.w);
    *(uint2*)(g_xnh + (size_t)r*HIDDEN + t*4) = pk.u;
}

// ----------------------------------------------- depthwise conv (k=3) + SiLU
__global__ __launch_bounds__(256) void conv_kernel(
    const float* __restrict__ cw, const float* __restrict__ cb)
{
    int idx = blockIdx.x * 256 + threadIdx.x;
    int d4 = idx & 511;
    int r  = idx >> 9;
    int l  = r & (SEQ - 1);
    const float* base = g_xz + (size_t)r*(2*INNER) + d4*4;
    float4 zero = make_float4(0.f, 0.f, 0.f, 0.f);
    float4 xm = (l > 0)       ? *(const float4*)(base - 2*INNER) : zero;
    float4 xc = *(const float4*)(base);
    float4 xp = (l < SEQ - 1) ? *(const float4*)(base + 2*INNER) : zero;
    const float4* cwp = (const float4*)(cw + d4*12);
    float4 t0 = cwp[0], t1 = cwp[1], t2 = cwp[2];
    float4 b4 = *(const float4*)(cb + d4*4);
    float o0 = t0.x*xm.x + t0.y*xc.x + t0.z*xp.x + b4.x;
    float o1 = t0.w*xm.y + t1.x*xc.y + t1.y*xp.y + b4.y;
    float o2 = t1.z*xm.z + t1.w*xc.z + t2.x*xp.z + b4.z;
    float o3 = t2.y*xm.w + t2.z*xc.w + t2.w*xp.w + b4.w;
    o0 *= __fdividef(1.f, 1.f + __expf(-o0));
    o1 *= __fdividef(1.f, 1.f + __expf(-o1));
    o2 *= __fdividef(1.f, 1.f + __expf(-o2));
    o3 *= __fdividef(1.f, 1.f + __expf(-o3));
    *(float4*)(g_xb + (size_t)r*INNER + d4*4) = make_float4(o0, o1, o2, o3);
    union { __nv_bfloat162 h[2]; uint2 u; } pk;
    pk.h[0] = __floats2bfloat162_rn(o0, o1);
    pk.h[1] = __floats2bfloat162_rn(o2, o3);
    *(uint2*)(g_xbh + (size_t)r*INNER + d4*4) = pk.u;
}

// ---------------------------- selective scan + gating -----------------------
__global__ __launch_bounds__(128) void scan_kernel(
    const float* __restrict__ A_log, const float* __restrict__ Dp)
{
    __shared__ float s_dt[2][16][16];
    __shared__ float s_x [2][16][16];
    __shared__ float s_z [2][16][16];
    __shared__ float s_bc[2][16][32];
    __shared__ float s_y [16][16];

    int tid = threadIdx.x;
    int b  = blockIdx.x >> 7;
    int d0 = (blockIdx.x & 127) * 16;
    int q  = tid & 7, dl = tid >> 3;
    int d  = d0 + dl;

    float a0 = -__expf(A_log[d*STATE + 2*q]);
    float a1 = -__expf(A_log[d*STATE + 2*q + 1]);
    float Dd = Dp[d];
    size_t tokbase = (size_t)b * SEQ;

    uint32_t u_dt = (uint32_t)__cvta_generic_to_shared(&s_dt[0][0][0]);
    uint32_t u_x  = (uint32_t)__cvta_generic_to_shared(&s_x [0][0][0]);
    uint32_t u_z  = (uint32_t)__cvta_generic_to_shared(&s_z [0][0][0]);
    uint32_t u_bc = (uint32_t)__cvta_generic_to_shared(&s_bc[0][0][0]);

    auto stage = [&](int s) {
        int l0 = s * 16, buf = s & 1;
        #pragma unroll
        for (int ii = tid; ii < 320; ii += 128) {
            if (ii < 192) {
                int arr = ii >> 6, e = ii & 63;
                int rowi = e >> 2, c4 = e & 3;
                size_t tok = tokbase + l0 + rowi;
                uint32_t doff = (uint32_t)((rowi*16 + c4*4) * 4) + buf*1024;
                if (arr == 0)
                    cp16(u_dt + doff, g_dtbc + tok*NCAT + d0 + c4*4);
                else if (arr == 1)
                    cp16(u_x + doff, g_xb + tok*INNER + d0 + c4*4);
                else
                    cp16(u_z + doff, g_xz + tok*(2*INNER) + INNER + d0 + c4*4);
            } else {
                int e = ii - 192;
                int rowi = e >> 3, c8 = e & 7;
                size_t tok = tokbase + l0 + rowi;
                cp16(u_bc + buf*2048 + (uint32_t)((rowi*32 + c8*4) * 4),
                     g_dtbc + tok*NCAT + 2048 + c8*4);
            }
        }
    };

    stage(0); cp_commit();

    float h0 = 0.f, h1 = 0.f;
    for (int s = 0; s < SEQ/16; s++) {
        if (s + 1 < SEQ/16) { stage(s + 1); cp_commit(); cp_wait<1>(); }
        else cp_wait<0>();
        __syncthreads();

        int buf = s & 1;
        #pragma unroll
        for (int i = 0; i < 16; i++) {
            float dtc = s_dt[buf][i][dl];
            float xc  = s_x [buf][i][dl];
            float2 Bv = *(const float2*)&s_bc[buf][i][2*q];
            float2 Cv = *(const float2*)&s_bc[buf][i][16 + 2*q];
            float e0 = __expf(dtc * a0);
            float e1 = __expf(dtc * a1);
            float dx = dtc * xc;
            h0 = fmaf(e0, h0, dx * Bv.x);
            h1 = fmaf(e1, h1, dx * Bv.y);
            float p = fmaf(h1, Cv.y, h0 * Cv.x);
            p += __shfl_xor_sync(0xffffffffu, p, 1);
            p += __shfl_xor_sync(0xffffffffu, p, 2);
            p += __shfl_xor_sync(0xffffffffu, p, 4);
            if (q == 0) {
                float zz  = s_z[buf][i][dl];
                float sil = zz * __fdividef(1.f, 1.f + __expf(-zz));
                s_y[i][dl] = fmaf(Dd, xc, p) * sil;
            }
        }
        __syncthreads();
        if (tid < 64) {
            int rowi = tid >> 2, c4 = tid & 3;
            float4 v = *(float4*)&s_y[rowi][c4*4];
            union { __nv_bfloat162 h[2]; uint2 u; } pk;
            pk.h[0] = __floats2bfloat162_rn(v.x, v.y);
            pk.h[1] = __floats2bfloat162_rn(v.z, v.w);
            *(uint2*)(g_yh + (tokbase + s*16 + rowi)*INNER + d0 + c4*4) = pk.u;
        }
    }
}

// ------------------------------------------------------------------- launch
extern "C" void kernel_launch(void* const* d_in, const int* in_sizes, int n_in,
                              void* d_out, int out_size)
{
    const float* x    = (const float*)d_in[0];
    const float* ns   = (const float*)d_in[1];
    const float* nb   = (const float*)d_in[2];
    const float* Win  = (const float*)d_in[3];
    const float* cw   = (const float*)d_in[4];
    const float* cb   = (const float*)d_in[5];
    const float* Wdt  = (const float*)d_in[6];
    const float* bdt  = (const float*)d_in[7];
    const float* Alog = (const float*)d_in[8];
    const float* Dp   = (const float*)d_in[9];
    const float* WB   = (const float*)d_in[10];
    const float* WC   = (const float*)d_in[11];
    const float* Wout = (const float*)d_in[12];
    float* out = (float*)d_out;

    void *p_xnh, *p_xz, *p_xbh, *p_dtbc, *p_yh, *p_winth, *p_wcatth, *p_woutth;
    cudaGetSymbolAddress(&p_xnh,  g_xnh);
    cudaGetSymbolAddress(&p_xz,   g_xz);
    cudaGetSymbolAddress(&p_xbh,  g_xbh);
    cudaGetSymbolAddress(&p_dtbc, g_dtbc);
    cudaGetSymbolAddress(&p_yh,   g_yh);
    cudaGetSymbolAddress(&p_winth,  g_WinTh);
    cudaGetSymbolAddress(&p_wcatth, g_WcatTh);
    cudaGetSymbolAddress(&p_woutth, g_WoutTh);
    __nv_bfloat16* xnh   = (__nv_bfloat16*)p_xnh;
    float*         xz    = (float*)p_xz;
    __nv_bfloat16* xbh   = (__nv_bfloat16*)p_xbh;
    float*         dtbc  = (float*)p_dtbc;
    __nv_bfloat16* yh    = (__nv_bfloat16*)p_yh;
    __nv_bfloat16* WinTh  = (__nv_bfloat16*)p_winth;
    __nv_bfloat16* WcatTh = (__nv_bfloat16*)p_wcatth;
    __nv_bfloat16* WoutTh = (__nv_bfloat16*)p_woutth;

    cudaFuncSetAttribute(gemm_bf16k<0>, cudaFuncAttributeMaxDynamicSharedMemorySize, GSMEMH);
    cudaFuncSetAttribute(gemm_bf16k<1>, cudaFuncAttributeMaxDynamicSharedMemorySize, GSMEMH);
    cudaFuncSetAttribute(gemm_bf16k<2>, cudaFuncAttributeMaxDynamicSharedMemorySize, GSMEMH);

    // launch order: gemm_bf16k<0> is the 4th launch (ncu target)
    // 1) Win -> WinTh (bf16)
    tr_bf16<<<dim3(2*INNER/32, HIDDEN/32), dim3(32,8)>>>(Win, WinTh, HIDDEN, 2*INNER);
    // 2) LayerNorm -> bf16
    ln_kernel<<<TOK, 256>>>(x, ns, nb);
    // 3) WB/WC rows of WcatTh
    wbc_kernel<<<(256*2048)/256, 256>>>(WB, WC);
    // 4) xz = xn @ W_in   (bf16 mma)  <-- profiled
    gemm_bf16k<0><<<dim3(2*INNER/256, TOK/128), 256, GSMEMH>>>(
        xnh, WinTh, xz, TOK, 2*INNER, HIDDEN, nullptr, nullptr);
    // 5) Wdt -> WcatTh rows 0..2047
    tr_bf16<<<dim3(INNER/32, INNER/32), dim3(32,8)>>>(Wdt, WcatTh, INNER, INNER);
    // 6) conv + SiLU (fp32 + bf16 outputs)
    conv_kernel<<<(TOK*INNER/4)/256, 256>>>(cw, cb);
    // 7) [dt | B | C] = xb @ Wcat  (bf16 mma, softplus on dt cols)
    gemm_bf16k<1><<<dim3(NCAT/256, TOK/128), 256, GSMEMH>>>(
        xbh, WcatTh, dtbc, TOK, NCAT, INNER, bdt, nullptr);
    // 8) Wout -> WoutTh (bf16)
    tr_bf16<<<dim3(HIDDEN/32, INNER/32), dim3(32,8)>>>(Wout, WoutTh, INNER, HIDDEN);
    // 9) selective scan + gating -> bf16 y
    scan_kernel<<<512, 128>>>(Alog, Dp);
    // 10) out = x + y @ W_out  (bf16 mma + fp32 residual)
    gemm_bf16k<2><<<dim3(HIDDEN/256, TOK/128), 256, GSMEMH>>>(
        yh, WoutTh, out, TOK, HIDDEN, INNER, nullptr, x);
}